// round 13
// baseline (speedup 1.0000x reference)
#include <cuda_runtime.h>
#include <cuda_bf16.h>
#include <cuda_fp16.h>
#include <cstdint>

#define BB 4
#define SS 4096
#define DD 1024
#define HH 64
#define NTOT 192

// Attention operands: Q single fp16 (carries 0.125*log2e), K fp16 hi/lo, V fp16.
__device__ __half g_Q16[BB * SS * HH];
__device__ __half g_K16h[BB * SS * HH];
__device__ __half g_K16l[BB * SS * HH];
__device__ __half g_V16[BB * SS * HH];
// W fp16 hi/lo, transposed to [N=192][K=1024]; Wq pre-scaled by 0.125*log2(e)
__device__ __half g_wh16[NTOT * DD];
__device__ __half g_wl16[NTOT * DD];

// ---------------------------------------------------------------------------
// Stable-PTX helpers (harness emits compute_103 PTX: no tcgen05 allowed)
// ---------------------------------------------------------------------------
__device__ __forceinline__ uint32_t smem_u32(const void* p) {
    uint32_t a;
    asm("{ .reg .u64 t; cvta.to.shared.u64 t, %1; cvt.u32.u64 %0, t; }" : "=r"(a) : "l"(p));
    return a;
}
__device__ __forceinline__ void mma_f16(float* c, const uint32_t* a, const uint32_t* b) {
    asm volatile(
        "mma.sync.aligned.m16n8k16.row.col.f32.f16.f16.f32 "
        "{%0,%1,%2,%3}, {%4,%5,%6,%7}, {%8,%9}, {%0,%1,%2,%3};"
        : "+f"(c[0]), "+f"(c[1]), "+f"(c[2]), "+f"(c[3])
        : "r"(a[0]), "r"(a[1]), "r"(a[2]), "r"(a[3]), "r"(b[0]), "r"(b[1]));
}
__device__ __forceinline__ void ldsm_x4(uint32_t* r, uint32_t addr) {
    asm volatile("ldmatrix.sync.aligned.m8n8.x4.shared.b16 {%0,%1,%2,%3}, [%4];"
                 : "=r"(r[0]), "=r"(r[1]), "=r"(r[2]), "=r"(r[3]) : "r"(addr));
}
__device__ __forceinline__ void ldsm_x4_t(uint32_t* r, uint32_t addr) {
    asm volatile("ldmatrix.sync.aligned.m8n8.x4.trans.shared.b16 {%0,%1,%2,%3}, [%4];"
                 : "=r"(r[0]), "=r"(r[1]), "=r"(r[2]), "=r"(r[3]) : "r"(addr));
}
__device__ __forceinline__ uint32_t pack_h2(float lo, float hi) {   // lo -> low half
    uint32_t r;
    asm("cvt.rn.f16x2.f32 %0, %1, %2;" : "=r"(r) : "f"(hi), "f"(lo));
    return r;
}
__device__ __forceinline__ uint32_t ex2_h2(uint32_t h2) {
    uint32_t r;
    asm("ex2.approx.f16x2 %0, %1;" : "=r"(r) : "r"(h2));
    return r;
}
__device__ __forceinline__ float ex2f(float x) {
    float r;
    asm("ex2.approx.f32 %0, %1;" : "=f"(r) : "f"(x));
    return r;
}
// v = hi + lo fp16 split of a float pair
__device__ __forceinline__ void split2h(float x, float y, uint32_t& hi, uint32_t& lo) {
    hi = pack_h2(x, y);
    float2 f = __half22float2(*(__half2*)&hi);
    lo = pack_h2(x - f.x, y - f.y);
}
#define CP_ASYNC16(dst, src) \
    asm volatile("cp.async.cg.shared.global [%0], [%1], 16;" :: "r"(dst), "l"(src) : "memory")
#define CP_COMMIT() asm volatile("cp.async.commit_group;" ::: "memory")
#define CP_WAIT0()  asm volatile("cp.async.wait_group 0;" ::: "memory")
#define GBAR(id)    asm volatile("bar.sync %0, 128;" :: "r"(id) : "memory")

// ---------------------------------------------------------------------------
// wconv: W fp32 [1024,64] x3 -> hi/lo fp16 [192,1024].
// Wq scaled by 0.125*log2(e) so attention scores are in log2 domain.
// ---------------------------------------------------------------------------
__global__ void wconv_kernel(const float* __restrict__ Wq,
                             const float* __restrict__ Wk,
                             const float* __restrict__ Wv)
{
    int i = blockIdx.x * 256 + threadIdx.x;
    if (i >= NTOT * DD) return;
    int n = i / DD, k = i - n * DD;
    int t = n >> 6, h = n & 63;
    const float* W = (t == 0) ? Wq : ((t == 1) ? Wk : Wv);
    float v = W[(size_t)k * HH + h] * ((t == 0) ? 0.125f * 1.4426950408889634f : 1.0f);
    __half hi = __float2half(v);
    g_wh16[i] = hi;
    g_wl16[i] = __float2half(v - __half2float(hi));
}

// ---------------------------------------------------------------------------
// QKV GEMM: C[16384,192] = x * W^T via 2-term fp16 HMMA (x fp16, W = wh+wl).
// KC=32 double-buffered: stage 35840B -> 2 CTAs resident/SM.
// Epilogue: Q -> fp16 single; K -> fp16 hi/lo; V -> fp16.
// ---------------------------------------------------------------------------
#define G_STG   35840
#define G_A     0
#define G_BH    5120
#define G_BL    20480

__global__ __launch_bounds__(256, 2) void qkv_mma_kernel(const float* __restrict__ x)
{
    extern __shared__ char smem[];
    const uint32_t sm0 = smem_u32(smem);
    const int tid = threadIdx.x;
    const int wid = tid >> 5, lane = tid & 31;
    const int wm = wid & 1, wn = wid >> 1;
    const int m0 = blockIdx.x * 64;

    const int li  = lane & 7;
    const int r16 = lane & 15;
    const int hfA = (lane >> 4) * 16;
    const int nh8 = ((lane >> 4) & 1) * 8;
    const int kh16 = ((lane >> 3) & 1) * 16;

    float acc[2][6][4];
    #pragma unroll
    for (int mi = 0; mi < 2; ++mi)
        #pragma unroll
        for (int j = 0; j < 6; ++j)
            #pragma unroll
            for (int q = 0; q < 4; ++q) acc[mi][j][q] = 0.0f;

    const int ar   = tid >> 2;          // A row 0..63
    const int ac0e = (tid & 3) * 8;     // A element offset 0,8,16,24

    float4 av[2];
    // ---- prologue: chunk 0 ----
    {
        const float* ap = x + (size_t)(m0 + ar) * DD + ac0e;
        av[0] = *(const float4*)ap;
        av[1] = *(const float4*)(ap + 4);
        #pragma unroll
        for (int i = 0; i < 3; ++i) {                  // 768 x 16B per array
            int id = tid + 256 * i, row = id >> 2, ch = id & 3;
            CP_ASYNC16(sm0 + G_BH + row * 80 + ch * 16, g_wh16 + (size_t)row * DD + ch * 8);
            CP_ASYNC16(sm0 + G_BL + row * 80 + ch * 16, g_wl16 + (size_t)row * DD + ch * 8);
        }
        CP_COMMIT();
        uint4 hv;
        hv.x = pack_h2(av[0].x, av[0].y);
        hv.y = pack_h2(av[0].z, av[0].w);
        hv.z = pack_h2(av[1].x, av[1].y);
        hv.w = pack_h2(av[1].z, av[1].w);
        *(uint4*)(smem + G_A + ar * 80 + ac0e * 2) = hv;
        CP_WAIT0();
        __syncthreads();
    }

    for (int c = 0; c < 32; ++c) {
        const int s = c & 1;
        const uint32_t sb = sm0 + s * G_STG;

        if (c < 31) {   // prefetch chunk c+1 into the other stage
            const float* ap = x + (size_t)(m0 + ar) * DD + (c + 1) * 32 + ac0e;
            av[0] = *(const float4*)ap;
            av[1] = *(const float4*)(ap + 4);
            const uint32_t ob = sm0 + (s ^ 1) * G_STG;
            #pragma unroll
            for (int i = 0; i < 3; ++i) {
                int id = tid + 256 * i, row = id >> 2, ch = id & 3;
                CP_ASYNC16(ob + G_BH + row * 80 + ch * 16,
                           g_wh16 + (size_t)row * DD + (c + 1) * 32 + ch * 8);
                CP_ASYNC16(ob + G_BL + row * 80 + ch * 16,
                           g_wl16 + (size_t)row * DD + (c + 1) * 32 + ch * 8);
            }
            CP_COMMIT();
        }

        // ---- consume stage s: 2 k16-steps ----
        #pragma unroll
        for (int kk = 0; kk < 2; ++kk) {
            uint32_t Af[2][4];
            #pragma unroll
            for (int mi = 0; mi < 2; ++mi) {
                uint32_t a = sb + G_A + (wm * 32 + mi * 16 + r16) * 80 + kk * 32 + hfA;
                ldsm_x4(Af[mi], a);
            }
            uint32_t Bh[6][2], Bl[6][2];
            #pragma unroll
            for (int j2 = 0; j2 < 3; ++j2) {
                uint32_t a = sb + (wn * 48 + j2 * 16 + li + nh8) * 80 + kk * 32 + kh16;
                ldsm_x4(&Bh[2 * j2][0], a + G_BH);
                ldsm_x4(&Bl[2 * j2][0], a + G_BL);
            }
            #pragma unroll
            for (int mi = 0; mi < 2; ++mi)
                #pragma unroll
                for (int j = 0; j < 6; ++j) {
                    mma_f16(acc[mi][j], Af[mi], Bh[j]);
                    mma_f16(acc[mi][j], Af[mi], Bl[j]);
                }
        }

        if (c < 31) {   // store converted A into the other stage
            char* st = smem + (s ^ 1) * G_STG;
            uint4 hv;
            hv.x = pack_h2(av[0].x, av[0].y);
            hv.y = pack_h2(av[0].z, av[0].w);
            hv.z = pack_h2(av[1].x, av[1].y);
            hv.w = pack_h2(av[1].z, av[1].w);
            *(uint4*)(st + G_A + ar * 80 + ac0e * 2) = hv;
        }
        CP_WAIT0();
        __syncthreads();
    }

    // ---- epilogue: Q -> fp16; K -> fp16 hi/lo; V -> fp16 ----
    const int g = lane >> 2, t2 = (lane & 3) * 2;
    #pragma unroll
    for (int mi = 0; mi < 2; ++mi) {
        #pragma unroll
        for (int j = 0; j < 6; ++j) {
            const int nG = wn * 48 + j * 8 + t2;
            const int tns = nG >> 6, h = nG & 63;
            const int rowA = m0 + wm * 32 + mi * 16 + g;
            if (tns == 0) {
                *(uint32_t*)&g_Q16[(size_t)rowA * HH + h] =
                    pack_h2(acc[mi][j][0], acc[mi][j][1]);
                *(uint32_t*)&g_Q16[(size_t)(rowA + 8) * HH + h] =
                    pack_h2(acc[mi][j][2], acc[mi][j][3]);
            } else if (tns == 2) {
                *(uint32_t*)&g_V16[(size_t)rowA * HH + h] =
                    pack_h2(acc[mi][j][0], acc[mi][j][1]);
                *(uint32_t*)&g_V16[(size_t)(rowA + 8) * HH + h] =
                    pack_h2(acc[mi][j][2], acc[mi][j][3]);
            } else {
                uint32_t hi, lo;
                split2h(acc[mi][j][0], acc[mi][j][1], hi, lo);
                *(uint32_t*)&g_K16h[(size_t)rowA * HH + h] = hi;
                *(uint32_t*)&g_K16l[(size_t)rowA * HH + h] = lo;
                split2h(acc[mi][j][2], acc[mi][j][3], hi, lo);
                *(uint32_t*)&g_K16h[(size_t)(rowA + 8) * HH + h] = hi;
                *(uint32_t*)&g_K16l[(size_t)(rowA + 8) * HH + h] = lo;
            }
        }
    }
}

// ---------------------------------------------------------------------------
// Attention: causal flash, split-KV across two 4-warp groups (256 threads).
// Per-group 3-stage ring; QK mma for tile t+1 issued BEFORE softmax(t) so the
// tensor pipe drains under the softmax latency chain. QK = 2-term fp16;
// softmax via ex2.f16x2; PV = 1-term fp16. grid (32,4): q-blocks {p, 63-p}.
// ---------------------------------------------------------------------------
#define A_Q   0
#define A_ST0 9216       // 6 stages (3 per group); per stage: Kh | Kl | V (fp16)
#define A_STG 27648
#define A_KH 0
#define A_KL 9216
#define A_V  18432
#define A_SMEM (A_ST0 + 6 * A_STG)    // 175104

__global__ __launch_bounds__(256, 1) void attn_mma_kernel(float* __restrict__ out)
{
    extern __shared__ char smem[];
    const uint32_t sm0 = smem_u32(smem);
    const int b = blockIdx.y, pid = blockIdx.x;
    const int tid = threadIdx.x;
    const int w = tid >> 5, lane = tid & 31;
    const int grp = w >> 2, wg = w & 3;      // group 0/1, warp-in-group 0..3
    const int gtid = tid & 127;              // thread id within group

    const int li   = lane & 7;
    const int r16  = lane & 15;
    const int hfA  = (lane >> 4) * 16;
    const int nh8  = ((lane >> 4) & 1) * 8;
    const int kh16 = ((lane >> 3) & 1) * 16;
    const int sh8  = ((lane >> 3) & 1) * 8;
    const int hh16 = ((lane >> 4) & 1) * 16;
    const int g = lane >> 2, t2 = (lane & 3) * 2;

    const size_t base = (size_t)b * SS * HH;

    // prefetch K/V tile kb into ring slot r of this group
    auto prefetch = [&](int kb, int r) {
        const uint32_t ob = sm0 + A_ST0 + (3 * grp + r) * A_STG;
        const size_t kvo = base + (size_t)kb * 64 * HH;
        #pragma unroll
        for (int i = 0; i < 12; ++i) {
            int id = gtid + 128 * i;
            int arr = id >> 9, rem = id & 511, row = rem >> 3, ch = rem & 7;
            const __half* src = (arr == 0) ? g_K16h : (arr == 1) ? g_K16l : g_V16;
            CP_ASYNC16(ob + arr * 9216 + row * 144 + ch * 16,
                       src + kvo + (size_t)row * HH + ch * 8);
        }
    };

    for (int pass = 0; pass < 2; ++pass) {
        const int qb = pass ? (63 - pid) : pid;
        const int ng = (qb >= grp) ? (((qb - grp) >> 1) + 1) : 0;

        // prologue: prefetch ring0 (kb=grp) and ring1 (kb=grp+2)
        if (ng > 0) prefetch(grp, 0);
        CP_COMMIT();
        if (ng > 1) prefetch(grp + 2, 1);
        CP_COMMIT();
        // load Q tile fp16 (all 256 threads; 512 chunks)
        {
            const size_t qo = base + (size_t)qb * 64 * HH;
            #pragma unroll
            for (int i = 0; i < 2; ++i) {
                int id = tid + 256 * i;
                int row = id >> 3, ch = id & 7;
                *(uint4*)(smem + A_Q + row * 144 + ch * 16) =
                    *(const uint4*)(g_Q16 + qo + (size_t)row * HH + ch * 8);
            }
        }
        CP_WAIT0();
        __syncthreads();

        uint32_t q16[4][4];
        #pragma unroll
        for (int kk = 0; kk < 4; ++kk) {
            uint32_t a = sm0 + A_Q + (wg * 16 + r16) * 144 + kk * 32 + hfA;
            ldsm_x4(q16[kk], a);
        }

        // S = q16 (Kh + Kl)^T into St (2 terms, log2-domain)
        auto qk_mma = [&](float (*St)[4], uint32_t sb) {
            #pragma unroll
            for (int j = 0; j < 8; ++j)
                #pragma unroll
                for (int q = 0; q < 4; ++q) St[j][q] = 0.0f;
            #pragma unroll
            for (int kk = 0; kk < 4; ++kk) {
                uint32_t Kh[8][2], Kl[8][2];
                #pragma unroll
                for (int n2 = 0; n2 < 4; ++n2) {
                    uint32_t a = sb + (n2 * 16 + li + nh8) * 144 + kk * 32 + kh16;
                    ldsm_x4(&Kh[2 * n2][0], a + A_KH);
                    ldsm_x4(&Kl[2 * n2][0], a + A_KL);
                }
                #pragma unroll
                for (int j = 0; j < 8; ++j) {
                    mma_f16(St[j], q16[kk], Kh[j]);
                    mma_f16(St[j], q16[kk], Kl[j]);
                }
            }
        };

        float O[8][4];
        float m_[2] = {-1e30f, -1e30f}, l_[2] = {0.0f, 0.0f};
        #pragma unroll
        for (int j = 0; j < 8; ++j)
            #pragma unroll
            for (int q = 0; q < 4; ++q) O[j][q] = 0.0f;

        float Sb[2][8][4];
        if (ng > 0)
            qk_mma(Sb[0], sm0 + A_ST0 + (3 * grp) * A_STG);

        for (int t = 0; t < ng; ++t) {
            const int cur = t & 1;
            const uint32_t sbc = sm0 + A_ST0 + (3 * grp + (t % 3)) * A_STG;

            // prefetch tile t+2 into ring[(t+2)%3] (= ring[t-1], freed by GBAR)
            if (t + 2 < ng) prefetch(grp + 2 * (t + 2), (t + 2) % 3);
            CP_COMMIT();

            // issue QK for tile t+1 before softmax(t): tensor pipe drains
            // under the softmax latency chain
            if (t + 1 < ng)
                qk_mma(Sb[cur ^ 1], sm0 + A_ST0 + (3 * grp + ((t + 1) % 3)) * A_STG);

            float (*S)[4] = Sb[cur];

            if (grp + 2 * t == qb) {   // diagonal tile: causal mask
                const int rA = wg * 16 + g, rB = rA + 8;
                #pragma unroll
                for (int j = 0; j < 8; ++j) {
                    const int c0 = j * 8 + t2;
                    if (c0 > rA)     S[j][0] = -1e30f;
                    if (c0 + 1 > rA) S[j][1] = -1e30f;
                    if (c0 > rB)     S[j][2] = -1e30f;
                    if (c0 + 1 > rB) S[j][3] = -1e30f;
                }
            }

            // ---- online softmax, exp2 domain; P emitted as fp16x2 frags ----
            float mx0 = fmaxf(S[0][0], S[0][1]);
            float mx1 = fmaxf(S[0][2], S[0][3]);
            #pragma unroll
            for (int j = 1; j < 8; ++j) {
                mx0 = fmaxf(mx0, fmaxf(S[j][0], S[j][1]));
                mx1 = fmaxf(mx1, fmaxf(S[j][2], S[j][3]));
            }
            mx0 = fmaxf(mx0, __shfl_xor_sync(0xffffffffu, mx0, 1));
            mx0 = fmaxf(mx0, __shfl_xor_sync(0xffffffffu, mx0, 2));
            mx1 = fmaxf(mx1, __shfl_xor_sync(0xffffffffu, mx1, 1));
            mx1 = fmaxf(mx1, __shfl_xor_sync(0xffffffffu, mx1, 2));
            const float mn0 = fmaxf(m_[0], mx0);
            const float mn1 = fmaxf(m_[1], mx1);
            const float corr0 = ex2f(m_[0] - mn0);
            const float corr1 = ex2f(m_[1] - mn1);
            m_[0] = mn0; m_[1] = mn1;

            uint32_t EA[8], EB[8];
            float rs0 = 0.0f, rs1 = 0.0f;
            #pragma unroll
            for (int j = 0; j < 8; ++j) {
                EA[j] = ex2_h2(pack_h2(S[j][0] - mn0, S[j][1] - mn0));
                EB[j] = ex2_h2(pack_h2(S[j][2] - mn1, S[j][3] - mn1));
                float2 fa = __half22float2(*(__half2*)&EA[j]);
                float2 fb = __half22float2(*(__half2*)&EB[j]);
                rs0 += fa.x + fa.y;
                rs1 += fb.x + fb.y;
            }
            rs0 += __shfl_xor_sync(0xffffffffu, rs0, 1);
            rs0 += __shfl_xor_sync(0xffffffffu, rs0, 2);
            rs1 += __shfl_xor_sync(0xffffffffu, rs1, 1);
            rs1 += __shfl_xor_sync(0xffffffffu, rs1, 2);
            l_[0] = l_[0] * corr0 + rs0;
            l_[1] = l_[1] * corr1 + rs1;
            #pragma unroll
            for (int j = 0; j < 8; ++j) {
                O[j][0] *= corr0; O[j][1] *= corr0;
                O[j][2] *= corr1; O[j][3] *= corr1;
            }

            // ---- O += P V, single-term fp16 ----
            #pragma unroll
            for (int kk = 0; kk < 4; ++kk) {
                uint32_t p[4] = {EA[2 * kk], EB[2 * kk], EA[2 * kk + 1], EB[2 * kk + 1]};
                uint32_t Vf[8][2];
                #pragma unroll
                for (int h2 = 0; h2 < 4; ++h2) {
                    uint32_t a = sbc + A_V + (kk * 16 + li + sh8) * 144 + h2 * 32 + hh16;
                    ldsm_x4_t(&Vf[2 * h2][0], a);
                }
                #pragma unroll
                for (int j = 0; j < 8; ++j)
                    mma_f16(O[j], p, Vf[j]);
            }

            CP_WAIT0();
            GBAR(1 + grp);       // group-local: ring[t] free for reuse
        }

        // ---- merge partials: group1 -> smem, group0 combines + writes ----
        __syncthreads();         // all tiles done; stage smem reusable
        float* mb = (float*)(smem + A_ST0);
        if (grp == 1) {
            float* slot = mb + gtid * 36;
            #pragma unroll
            for (int j = 0; j < 8; ++j)
                #pragma unroll
                for (int q = 0; q < 4; ++q) slot[j * 4 + q] = O[j][q];
            slot[32] = m_[0]; slot[33] = m_[1];
            slot[34] = l_[0]; slot[35] = l_[1];
        }
        __syncthreads();
        if (grp == 0) {
            const float* slot = mb + gtid * 36;
            const float m1a = slot[32], m1b = slot[33];
            const float l1a = slot[34], l1b = slot[35];
            const float mnA = fmaxf(m_[0], m1a), mnB = fmaxf(m_[1], m1b);
            const float c00 = ex2f(m_[0] - mnA), c01 = ex2f(m1a - mnA);
            const float c10 = ex2f(m_[1] - mnB), c11 = ex2f(m1b - mnB);
            const float iA = 1.0f / (l_[0] * c00 + l1a * c01);
            const float iB = 1.0f / (l_[1] * c10 + l1b * c11);
            const int rowA = qb * 64 + wg * 16 + g;
            float* ob = out + (size_t)b * SS * HH;
            #pragma unroll
            for (int j = 0; j < 8; ++j) {
                const int col = j * 8 + t2;
                float2 v0, v1;
                v0.x = (O[j][0] * c00 + slot[j * 4 + 0] * c01) * iA;
                v0.y = (O[j][1] * c00 + slot[j * 4 + 1] * c01) * iA;
                v1.x = (O[j][2] * c10 + slot[j * 4 + 2] * c11) * iB;
                v1.y = (O[j][3] * c10 + slot[j * 4 + 3] * c11) * iB;
                *(float2*)&ob[(size_t)rowA * HH + col] = v0;
                *(float2*)&ob[(size_t)(rowA + 8) * HH + col] = v1;
            }
        }
        __syncthreads();         // before next pass overwrites Q smem / stages
    }
}

// ---------------------------------------------------------------------------
extern "C" void kernel_launch(void* const* d_in, const int* in_sizes, int n_in,
                              void* d_out, int out_size)
{
    (void)in_sizes; (void)n_in; (void)out_size;
    const float* x  = (const float*)d_in[0];
    const float* Wq = (const float*)d_in[1];
    const float* Wk = (const float*)d_in[2];
    const float* Wv = (const float*)d_in[3];
    float* out = (float*)d_out;

    static int attr_set = 0;
    const int gemm_smem = 2 * G_STG;                // 71680 -> 2 CTAs/SM
    const int attn_smem = A_SMEM;                   // 175104
    if (!attr_set) {
        cudaFuncSetAttribute(qkv_mma_kernel,
                             cudaFuncAttributeMaxDynamicSharedMemorySize, gemm_smem);
        cudaFuncSetAttribute(attn_mma_kernel,
                             cudaFuncAttributeMaxDynamicSharedMemorySize, attn_smem);
        attr_set = 1;
    }

    wconv_kernel<<<(NTOT * DD + 255) / 256, 256>>>(Wq, Wk, Wv);
    qkv_mma_kernel<<<SS * BB / 64, 256, gemm_smem>>>(x);
    attn_mma_kernel<<<dim3(32, 4), 256, attn_smem>>>(out);
}

// round 14
// speedup vs baseline: 1.1157x; 1.1157x over previous
#include <cuda_runtime.h>
#include <cuda_bf16.h>
#include <cuda_fp16.h>
#include <cstdint>

#define BB 4
#define SS 4096
#define DD 1024
#define HH 64
#define NTOT 192

// Attention operands: Q single fp16 (carries 0.125*log2e), K fp16 hi/lo, V fp16.
__device__ __half g_Q16[BB * SS * HH];
__device__ __half g_K16h[BB * SS * HH];
__device__ __half g_K16l[BB * SS * HH];
__device__ __half g_V16[BB * SS * HH];
// W fp16 hi/lo, transposed to [N=192][K=1024]; Wq pre-scaled by 0.125*log2(e)
__device__ __half g_wh16[NTOT * DD];
__device__ __half g_wl16[NTOT * DD];

// ---------------------------------------------------------------------------
// Stable-PTX helpers (harness emits compute_103 PTX: no tcgen05 allowed)
// ---------------------------------------------------------------------------
__device__ __forceinline__ uint32_t smem_u32(const void* p) {
    uint32_t a;
    asm("{ .reg .u64 t; cvta.to.shared.u64 t, %1; cvt.u32.u64 %0, t; }" : "=r"(a) : "l"(p));
    return a;
}
__device__ __forceinline__ void mma_f16(float* c, const uint32_t* a, const uint32_t* b) {
    asm volatile(
        "mma.sync.aligned.m16n8k16.row.col.f32.f16.f16.f32 "
        "{%0,%1,%2,%3}, {%4,%5,%6,%7}, {%8,%9}, {%0,%1,%2,%3};"
        : "+f"(c[0]), "+f"(c[1]), "+f"(c[2]), "+f"(c[3])
        : "r"(a[0]), "r"(a[1]), "r"(a[2]), "r"(a[3]), "r"(b[0]), "r"(b[1]));
}
__device__ __forceinline__ void ldsm_x4(uint32_t* r, uint32_t addr) {
    asm volatile("ldmatrix.sync.aligned.m8n8.x4.shared.b16 {%0,%1,%2,%3}, [%4];"
                 : "=r"(r[0]), "=r"(r[1]), "=r"(r[2]), "=r"(r[3]) : "r"(addr));
}
__device__ __forceinline__ void ldsm_x4_t(uint32_t* r, uint32_t addr) {
    asm volatile("ldmatrix.sync.aligned.m8n8.x4.trans.shared.b16 {%0,%1,%2,%3}, [%4];"
                 : "=r"(r[0]), "=r"(r[1]), "=r"(r[2]), "=r"(r[3]) : "r"(addr));
}
__device__ __forceinline__ uint32_t pack_h2(float lo, float hi) {   // lo -> low half
    uint32_t r;
    asm("cvt.rn.f16x2.f32 %0, %1, %2;" : "=r"(r) : "f"(hi), "f"(lo));
    return r;
}
__device__ __forceinline__ uint32_t ex2_h2(uint32_t h2) {
    uint32_t r;
    asm("ex2.approx.f16x2 %0, %1;" : "=r"(r) : "r"(h2));
    return r;
}
__device__ __forceinline__ float ex2f(float x) {
    float r;
    asm("ex2.approx.f32 %0, %1;" : "=f"(r) : "f"(x));
    return r;
}
// v = hi + lo fp16 split of a float pair
__device__ __forceinline__ void split2h(float x, float y, uint32_t& hi, uint32_t& lo) {
    hi = pack_h2(x, y);
    float2 f = __half22float2(*(__half2*)&hi);
    lo = pack_h2(x - f.x, y - f.y);
}
#define CP_ASYNC16(dst, src) \
    asm volatile("cp.async.cg.shared.global [%0], [%1], 16;" :: "r"(dst), "l"(src) : "memory")
#define CP_COMMIT() asm volatile("cp.async.commit_group;" ::: "memory")
#define CP_WAIT0()  asm volatile("cp.async.wait_group 0;" ::: "memory")
#define GBAR(id)    asm volatile("bar.sync %0, 128;" :: "r"(id) : "memory")

// ---------------------------------------------------------------------------
// wconv: W fp32 [1024,64] x3 -> hi/lo fp16 [192,1024].
// Wq scaled by 0.125*log2(e) so attention scores are in log2 domain.
// ---------------------------------------------------------------------------
__global__ void wconv_kernel(const float* __restrict__ Wq,
                             const float* __restrict__ Wk,
                             const float* __restrict__ Wv)
{
    int i = blockIdx.x * 256 + threadIdx.x;
    if (i >= NTOT * DD) return;
    int n = i / DD, k = i - n * DD;
    int t = n >> 6, h = n & 63;
    const float* W = (t == 0) ? Wq : ((t == 1) ? Wk : Wv);
    float v = W[(size_t)k * HH + h] * ((t == 0) ? 0.125f * 1.4426950408889634f : 1.0f);
    __half hi = __float2half(v);
    g_wh16[i] = hi;
    g_wl16[i] = __float2half(v - __half2float(hi));
}

// ---------------------------------------------------------------------------
// QKV GEMM (kept from R12): C = x * W^T via 2-term fp16 HMMA (x fp16, W=wh+wl).
// KC=32 double-buffered: stage 35840B -> 2 CTAs resident/SM.
// Epilogue: Q -> fp16 single; K -> fp16 hi/lo; V -> fp16.
// ---------------------------------------------------------------------------
#define G_STG   35840
#define G_A     0
#define G_BH    5120
#define G_BL    20480

__global__ __launch_bounds__(256, 2) void qkv_mma_kernel(const float* __restrict__ x)
{
    extern __shared__ char smem[];
    const uint32_t sm0 = smem_u32(smem);
    const int tid = threadIdx.x;
    const int wid = tid >> 5, lane = tid & 31;
    const int wm = wid & 1, wn = wid >> 1;
    const int m0 = blockIdx.x * 64;

    const int li  = lane & 7;
    const int r16 = lane & 15;
    const int hfA = (lane >> 4) * 16;
    const int nh8 = ((lane >> 4) & 1) * 8;
    const int kh16 = ((lane >> 3) & 1) * 16;

    float acc[2][6][4];
    #pragma unroll
    for (int mi = 0; mi < 2; ++mi)
        #pragma unroll
        for (int j = 0; j < 6; ++j)
            #pragma unroll
            for (int q = 0; q < 4; ++q) acc[mi][j][q] = 0.0f;

    const int ar   = tid >> 2;          // A row 0..63
    const int ac0e = (tid & 3) * 8;     // A element offset 0,8,16,24

    float4 av[2];
    // ---- prologue: chunk 0 ----
    {
        const float* ap = x + (size_t)(m0 + ar) * DD + ac0e;
        av[0] = *(const float4*)ap;
        av[1] = *(const float4*)(ap + 4);
        #pragma unroll
        for (int i = 0; i < 3; ++i) {                  // 768 x 16B per array
            int id = tid + 256 * i, row = id >> 2, ch = id & 3;
            CP_ASYNC16(sm0 + G_BH + row * 80 + ch * 16, g_wh16 + (size_t)row * DD + ch * 8);
            CP_ASYNC16(sm0 + G_BL + row * 80 + ch * 16, g_wl16 + (size_t)row * DD + ch * 8);
        }
        CP_COMMIT();
        uint4 hv;
        hv.x = pack_h2(av[0].x, av[0].y);
        hv.y = pack_h2(av[0].z, av[0].w);
        hv.z = pack_h2(av[1].x, av[1].y);
        hv.w = pack_h2(av[1].z, av[1].w);
        *(uint4*)(smem + G_A + ar * 80 + ac0e * 2) = hv;
        CP_WAIT0();
        __syncthreads();
    }

    for (int c = 0; c < 32; ++c) {
        const int s = c & 1;
        const uint32_t sb = sm0 + s * G_STG;

        if (c < 31) {   // prefetch chunk c+1 into the other stage
            const float* ap = x + (size_t)(m0 + ar) * DD + (c + 1) * 32 + ac0e;
            av[0] = *(const float4*)ap;
            av[1] = *(const float4*)(ap + 4);
            const uint32_t ob = sm0 + (s ^ 1) * G_STG;
            #pragma unroll
            for (int i = 0; i < 3; ++i) {
                int id = tid + 256 * i, row = id >> 2, ch = id & 3;
                CP_ASYNC16(ob + G_BH + row * 80 + ch * 16,
                           g_wh16 + (size_t)row * DD + (c + 1) * 32 + ch * 8);
                CP_ASYNC16(ob + G_BL + row * 80 + ch * 16,
                           g_wl16 + (size_t)row * DD + (c + 1) * 32 + ch * 8);
            }
            CP_COMMIT();
        }

        // ---- consume stage s: 2 k16-steps ----
        #pragma unroll
        for (int kk = 0; kk < 2; ++kk) {
            uint32_t Af[2][4];
            #pragma unroll
            for (int mi = 0; mi < 2; ++mi) {
                uint32_t a = sb + G_A + (wm * 32 + mi * 16 + r16) * 80 + kk * 32 + hfA;
                ldsm_x4(Af[mi], a);
            }
            uint32_t Bh[6][2], Bl[6][2];
            #pragma unroll
            for (int j2 = 0; j2 < 3; ++j2) {
                uint32_t a = sb + (wn * 48 + j2 * 16 + li + nh8) * 80 + kk * 32 + kh16;
                ldsm_x4(&Bh[2 * j2][0], a + G_BH);
                ldsm_x4(&Bl[2 * j2][0], a + G_BL);
            }
            #pragma unroll
            for (int mi = 0; mi < 2; ++mi)
                #pragma unroll
                for (int j = 0; j < 6; ++j) {
                    mma_f16(acc[mi][j], Af[mi], Bh[j]);
                    mma_f16(acc[mi][j], Af[mi], Bl[j]);
                }
        }

        if (c < 31) {   // store converted A into the other stage
            char* st = smem + (s ^ 1) * G_STG;
            uint4 hv;
            hv.x = pack_h2(av[0].x, av[0].y);
            hv.y = pack_h2(av[0].z, av[0].w);
            hv.z = pack_h2(av[1].x, av[1].y);
            hv.w = pack_h2(av[1].z, av[1].w);
            *(uint4*)(st + G_A + ar * 80 + ac0e * 2) = hv;
        }
        CP_WAIT0();
        __syncthreads();
    }

    // ---- epilogue: Q -> fp16; K -> fp16 hi/lo; V -> fp16 ----
    const int g = lane >> 2, t2 = (lane & 3) * 2;
    #pragma unroll
    for (int mi = 0; mi < 2; ++mi) {
        #pragma unroll
        for (int j = 0; j < 6; ++j) {
            const int nG = wn * 48 + j * 8 + t2;
            const int tns = nG >> 6, h = nG & 63;
            const int rowA = m0 + wm * 32 + mi * 16 + g;
            if (tns == 0) {
                *(uint32_t*)&g_Q16[(size_t)rowA * HH + h] =
                    pack_h2(acc[mi][j][0], acc[mi][j][1]);
                *(uint32_t*)&g_Q16[(size_t)(rowA + 8) * HH + h] =
                    pack_h2(acc[mi][j][2], acc[mi][j][3]);
            } else if (tns == 2) {
                *(uint32_t*)&g_V16[(size_t)rowA * HH + h] =
                    pack_h2(acc[mi][j][0], acc[mi][j][1]);
                *(uint32_t*)&g_V16[(size_t)(rowA + 8) * HH + h] =
                    pack_h2(acc[mi][j][2], acc[mi][j][3]);
            } else {
                uint32_t hi, lo;
                split2h(acc[mi][j][0], acc[mi][j][1], hi, lo);
                *(uint32_t*)&g_K16h[(size_t)rowA * HH + h] = hi;
                *(uint32_t*)&g_K16l[(size_t)rowA * HH + h] = lo;
                split2h(acc[mi][j][2], acc[mi][j][3], hi, lo);
                *(uint32_t*)&g_K16h[(size_t)(rowA + 8) * HH + h] = hi;
                *(uint32_t*)&g_K16l[(size_t)(rowA + 8) * HH + h] = lo;
            }
        }
    }
}

// ---------------------------------------------------------------------------
// Attention (reverted to R11): causal flash, split-KV across two 4-warp groups.
// QK = 2-term fp16 (q16 x (Kh+Kl)); softmax via ex2.f16x2; PV = 1-term fp16.
// grid (32,4): CTA handles q-blocks {p, 63-p}; group g does kb ≡ g (mod 2).
// ---------------------------------------------------------------------------
#define A_Q   0
#define A_ST0 9216       // 4 stages (2 per group); per stage: Kh | Kl | V (fp16)
#define A_STG 27648
#define A_KH 0
#define A_KL 9216
#define A_V  18432
#define A_SMEM (A_ST0 + 4 * A_STG)    // 119808

__global__ __launch_bounds__(256, 1) void attn_mma_kernel(float* __restrict__ out)
{
    extern __shared__ char smem[];
    const uint32_t sm0 = smem_u32(smem);
    const int b = blockIdx.y, pid = blockIdx.x;
    const int tid = threadIdx.x;
    const int w = tid >> 5, lane = tid & 31;
    const int grp = w >> 2, wg = w & 3;      // group 0/1, warp-in-group 0..3
    const int gtid = tid & 127;              // thread id within group

    const int li   = lane & 7;
    const int r16  = lane & 15;
    const int hfA  = (lane >> 4) * 16;
    const int nh8  = ((lane >> 4) & 1) * 8;
    const int kh16 = ((lane >> 3) & 1) * 16;
    const int sh8  = ((lane >> 3) & 1) * 8;
    const int hh16 = ((lane >> 4) & 1) * 16;
    const int g = lane >> 2, t2 = (lane & 3) * 2;

    const size_t base = (size_t)b * SS * HH;

    for (int pass = 0; pass < 2; ++pass) {
        const int qb = pass ? (63 - pid) : pid;
        const int ng = (qb >= grp) ? (((qb - grp) >> 1) + 1) : 0;

        // prefetch this group's first tile (kb = grp) into its stage 0
        if (ng > 0) {
            const uint32_t ob = sm0 + A_ST0 + (2 * grp) * A_STG;
            const size_t kvo = base + (size_t)grp * 64 * HH;
            #pragma unroll
            for (int i = 0; i < 12; ++i) {
                int id = gtid + 128 * i;
                int arr = id >> 9, rem = id & 511, row = rem >> 3, ch = rem & 7;
                const __half* src = (arr == 0) ? g_K16h : (arr == 1) ? g_K16l : g_V16;
                CP_ASYNC16(ob + arr * 9216 + row * 144 + ch * 16,
                           src + kvo + (size_t)row * HH + ch * 8);
            }
        }
        CP_COMMIT();
        // load Q tile fp16 (all 256 threads; 512 chunks)
        {
            const size_t qo = base + (size_t)qb * 64 * HH;
            #pragma unroll
            for (int i = 0; i < 2; ++i) {
                int id = tid + 256 * i;
                int row = id >> 3, ch = id & 7;
                *(uint4*)(smem + A_Q + row * 144 + ch * 16) =
                    *(const uint4*)(g_Q16 + qo + (size_t)row * HH + ch * 8);
            }
        }
        CP_WAIT0();
        __syncthreads();

        uint32_t q16[4][4];
        #pragma unroll
        for (int kk = 0; kk < 4; ++kk) {
            uint32_t a = sm0 + A_Q + (wg * 16 + r16) * 144 + kk * 32 + hfA;
            ldsm_x4(q16[kk], a);
        }

        float O[8][4];
        float m_[2] = {-1e30f, -1e30f}, l_[2] = {0.0f, 0.0f};
        #pragma unroll
        for (int j = 0; j < 8; ++j)
            #pragma unroll
            for (int q = 0; q < 4; ++q) O[j][q] = 0.0f;

        for (int t = 0; t < ng; ++t) {
            const int kb = grp + 2 * t;
            const int s = t & 1;
            const uint32_t sb = sm0 + A_ST0 + (2 * grp + s) * A_STG;

            if (t + 1 < ng) {     // prefetch this group's next tile (kb+2)
                const uint32_t ob = sm0 + A_ST0 + (2 * grp + (s ^ 1)) * A_STG;
                const size_t kvo = base + (size_t)(kb + 2) * 64 * HH;
                #pragma unroll
                for (int i = 0; i < 12; ++i) {
                    int id = gtid + 128 * i;
                    int arr = id >> 9, rem = id & 511, row = rem >> 3, ch = rem & 7;
                    const __half* src = (arr == 0) ? g_K16h : (arr == 1) ? g_K16l : g_V16;
                    CP_ASYNC16(ob + arr * 9216 + row * 144 + ch * 16,
                               src + kvo + (size_t)row * HH + ch * 8);
                }
                CP_COMMIT();
            }

            // ---- S = q16 (Kh + Kl)^T, 2 terms (log2-domain) ----
            float S[8][4];
            #pragma unroll
            for (int j = 0; j < 8; ++j)
                #pragma unroll
                for (int q = 0; q < 4; ++q) S[j][q] = 0.0f;

            #pragma unroll
            for (int kk = 0; kk < 4; ++kk) {
                uint32_t Kh[8][2], Kl[8][2];
                #pragma unroll
                for (int n2 = 0; n2 < 4; ++n2) {
                    uint32_t a = sb + (n2 * 16 + li + nh8) * 144 + kk * 32 + kh16;
                    ldsm_x4(&Kh[2 * n2][0], a + A_KH);
                    ldsm_x4(&Kl[2 * n2][0], a + A_KL);
                }
                #pragma unroll
                for (int j = 0; j < 8; ++j) {
                    mma_f16(S[j], q16[kk], Kh[j]);
                    mma_f16(S[j], q16[kk], Kl[j]);
                }
            }

            if (kb == qb) {       // diagonal tile: causal mask (local coords)
                const int rA = wg * 16 + g, rB = rA + 8;
                #pragma unroll
                for (int j = 0; j < 8; ++j) {
                    const int c0 = j * 8 + t2;
                    if (c0 > rA)     S[j][0] = -1e30f;
                    if (c0 + 1 > rA) S[j][1] = -1e30f;
                    if (c0 > rB)     S[j][2] = -1e30f;
                    if (c0 + 1 > rB) S[j][3] = -1e30f;
                }
            }

            // ---- online softmax, exp2 domain; P emitted as fp16x2 frags ----
            float mx0 = fmaxf(S[0][0], S[0][1]);
            float mx1 = fmaxf(S[0][2], S[0][3]);
            #pragma unroll
            for (int j = 1; j < 8; ++j) {
                mx0 = fmaxf(mx0, fmaxf(S[j][0], S[j][1]));
                mx1 = fmaxf(mx1, fmaxf(S[j][2], S[j][3]));
            }
            mx0 = fmaxf(mx0, __shfl_xor_sync(0xffffffffu, mx0, 1));
            mx0 = fmaxf(mx0, __shfl_xor_sync(0xffffffffu, mx0, 2));
            mx1 = fmaxf(mx1, __shfl_xor_sync(0xffffffffu, mx1, 1));
            mx1 = fmaxf(mx1, __shfl_xor_sync(0xffffffffu, mx1, 2));
            const float mn0 = fmaxf(m_[0], mx0);
            const float mn1 = fmaxf(m_[1], mx1);
            const float corr0 = ex2f(m_[0] - mn0);
            const float corr1 = ex2f(m_[1] - mn1);
            m_[0] = mn0; m_[1] = mn1;

            uint32_t EA[8], EB[8];
            float rs0 = 0.0f, rs1 = 0.0f;
            #pragma unroll
            for (int j = 0; j < 8; ++j) {
                EA[j] = ex2_h2(pack_h2(S[j][0] - mn0, S[j][1] - mn0));
                EB[j] = ex2_h2(pack_h2(S[j][2] - mn1, S[j][3] - mn1));
                float2 fa = __half22float2(*(__half2*)&EA[j]);
                float2 fb = __half22float2(*(__half2*)&EB[j]);
                rs0 += fa.x + fa.y;
                rs1 += fb.x + fb.y;
            }
            rs0 += __shfl_xor_sync(0xffffffffu, rs0, 1);
            rs0 += __shfl_xor_sync(0xffffffffu, rs0, 2);
            rs1 += __shfl_xor_sync(0xffffffffu, rs1, 1);
            rs1 += __shfl_xor_sync(0xffffffffu, rs1, 2);
            l_[0] = l_[0] * corr0 + rs0;
            l_[1] = l_[1] * corr1 + rs1;
            #pragma unroll
            for (int j = 0; j < 8; ++j) {
                O[j][0] *= corr0; O[j][1] *= corr0;
                O[j][2] *= corr1; O[j][3] *= corr1;
            }

            // ---- O += P V, single-term fp16 ----
            #pragma unroll
            for (int kk = 0; kk < 4; ++kk) {
                uint32_t p[4] = {EA[2 * kk], EB[2 * kk], EA[2 * kk + 1], EB[2 * kk + 1]};
                uint32_t Vf[8][2];
                #pragma unroll
                for (int h2 = 0; h2 < 4; ++h2) {
                    uint32_t a = sb + A_V + (kk * 16 + li + sh8) * 144 + h2 * 32 + hh16;
                    ldsm_x4_t(&Vf[2 * h2][0], a);
                }
                #pragma unroll
                for (int j = 0; j < 8; ++j)
                    mma_f16(O[j], p, Vf[j]);
            }

            CP_WAIT0();
            GBAR(1 + grp);       // group-local barrier (stages are per-group)
        }

        // ---- merge partials: group1 -> smem, group0 combines + writes ----
        __syncthreads();         // all tiles done; stage smem reusable
        float* mb = (float*)(smem + A_ST0);
        if (grp == 1) {
            float* slot = mb + gtid * 36;
            #pragma unroll
            for (int j = 0; j < 8; ++j)
                #pragma unroll
                for (int q = 0; q < 4; ++q) slot[j * 4 + q] = O[j][q];
            slot[32] = m_[0]; slot[33] = m_[1];
            slot[34] = l_[0]; slot[35] = l_[1];
        }
        __syncthreads();
        if (grp == 0) {
            const float* slot = mb + gtid * 36;
            const float m1a = slot[32], m1b = slot[33];
            const float l1a = slot[34], l1b = slot[35];
            const float mnA = fmaxf(m_[0], m1a), mnB = fmaxf(m_[1], m1b);
            const float c00 = ex2f(m_[0] - mnA), c01 = ex2f(m1a - mnA);
            const float c10 = ex2f(m_[1] - mnB), c11 = ex2f(m1b - mnB);
            const float iA = 1.0f / (l_[0] * c00 + l1a * c01);
            const float iB = 1.0f / (l_[1] * c10 + l1b * c11);
            const int rowA = qb * 64 + wg * 16 + g;
            float* ob = out + (size_t)b * SS * HH;
            #pragma unroll
            for (int j = 0; j < 8; ++j) {
                const int col = j * 8 + t2;
                float2 v0, v1;
                v0.x = (O[j][0] * c00 + slot[j * 4 + 0] * c01) * iA;
                v0.y = (O[j][1] * c00 + slot[j * 4 + 1] * c01) * iA;
                v1.x = (O[j][2] * c10 + slot[j * 4 + 2] * c11) * iB;
                v1.y = (O[j][3] * c10 + slot[j * 4 + 3] * c11) * iB;
                *(float2*)&ob[(size_t)rowA * HH + col] = v0;
                *(float2*)&ob[(size_t)(rowA + 8) * HH + col] = v1;
            }
        }
        __syncthreads();         // before next pass overwrites Q smem / stages
    }
}

// ---------------------------------------------------------------------------
extern "C" void kernel_launch(void* const* d_in, const int* in_sizes, int n_in,
                              void* d_out, int out_size)
{
    (void)in_sizes; (void)n_in; (void)out_size;
    const float* x  = (const float*)d_in[0];
    const float* Wq = (const float*)d_in[1];
    const float* Wk = (const float*)d_in[2];
    const float* Wv = (const float*)d_in[3];
    float* out = (float*)d_out;

    static int attr_set = 0;
    const int gemm_smem = 2 * G_STG;                // 71680 -> 2 CTAs/SM
    const int attn_smem = A_SMEM;                   // 119808
    if (!attr_set) {
        cudaFuncSetAttribute(qkv_mma_kernel,
                             cudaFuncAttributeMaxDynamicSharedMemorySize, gemm_smem);
        cudaFuncSetAttribute(attn_mma_kernel,
                             cudaFuncAttributeMaxDynamicSharedMemorySize, attn_smem);
        attr_set = 1;
    }

    wconv_kernel<<<(NTOT * DD + 255) / 256, 256>>>(Wq, Wk, Wv);
    qkv_mma_kernel<<<SS * BB / 64, 256, gemm_smem>>>(x);
    attn_mma_kernel<<<dim3(32, 4), 256, attn_smem>>>(out);
}

// round 15
// speedup vs baseline: 1.1607x; 1.0403x over previous
#include <cuda_runtime.h>
#include <cuda_bf16.h>
#include <cuda_fp16.h>
#include <cstdint>

#define BB 4
#define SS 4096
#define DD 1024
#define HH 64
#define NTOT 192

// Attention operands: Q single fp16 (carries 0.125*log2e), K fp16 hi/lo, V fp16.
__device__ __half g_Q16[BB * SS * HH];
__device__ __half g_K16h[BB * SS * HH];
__device__ __half g_K16l[BB * SS * HH];
__device__ __half g_V16[BB * SS * HH];
// W fp16 hi/lo, transposed to [N=192][K=1024]; Wq pre-scaled by 0.125*log2(e)
__device__ __half g_wh16[NTOT * DD];
__device__ __half g_wl16[NTOT * DD];

// ---------------------------------------------------------------------------
// Stable-PTX helpers (harness emits compute_103 PTX: no tcgen05 allowed)
// ---------------------------------------------------------------------------
__device__ __forceinline__ uint32_t smem_u32(const void* p) {
    uint32_t a;
    asm("{ .reg .u64 t; cvta.to.shared.u64 t, %1; cvt.u32.u64 %0, t; }" : "=r"(a) : "l"(p));
    return a;
}
__device__ __forceinline__ void mma_f16(float* c, const uint32_t* a, const uint32_t* b) {
    asm volatile(
        "mma.sync.aligned.m16n8k16.row.col.f32.f16.f16.f32 "
        "{%0,%1,%2,%3}, {%4,%5,%6,%7}, {%8,%9}, {%0,%1,%2,%3};"
        : "+f"(c[0]), "+f"(c[1]), "+f"(c[2]), "+f"(c[3])
        : "r"(a[0]), "r"(a[1]), "r"(a[2]), "r"(a[3]), "r"(b[0]), "r"(b[1]));
}
__device__ __forceinline__ void ldsm_x4(uint32_t* r, uint32_t addr) {
    asm volatile("ldmatrix.sync.aligned.m8n8.x4.shared.b16 {%0,%1,%2,%3}, [%4];"
                 : "=r"(r[0]), "=r"(r[1]), "=r"(r[2]), "=r"(r[3]) : "r"(addr));
}
__device__ __forceinline__ void ldsm_x4_t(uint32_t* r, uint32_t addr) {
    asm volatile("ldmatrix.sync.aligned.m8n8.x4.trans.shared.b16 {%0,%1,%2,%3}, [%4];"
                 : "=r"(r[0]), "=r"(r[1]), "=r"(r[2]), "=r"(r[3]) : "r"(addr));
}
__device__ __forceinline__ uint32_t pack_h2(float lo, float hi) {   // lo -> low half
    uint32_t r;
    asm("cvt.rn.f16x2.f32 %0, %1, %2;" : "=r"(r) : "f"(hi), "f"(lo));
    return r;
}
__device__ __forceinline__ uint32_t ex2_h2(uint32_t h2) {
    uint32_t r;
    asm("ex2.approx.f16x2 %0, %1;" : "=r"(r) : "r"(h2));
    return r;
}
__device__ __forceinline__ float ex2f(float x) {
    float r;
    asm("ex2.approx.f32 %0, %1;" : "=f"(r) : "f"(x));
    return r;
}
// v = hi + lo fp16 split of a float pair
__device__ __forceinline__ void split2h(float x, float y, uint32_t& hi, uint32_t& lo) {
    hi = pack_h2(x, y);
    float2 f = __half22float2(*(__half2*)&hi);
    lo = pack_h2(x - f.x, y - f.y);
}
#define CP_ASYNC16(dst, src) \
    asm volatile("cp.async.cg.shared.global [%0], [%1], 16;" :: "r"(dst), "l"(src) : "memory")
#define CP_COMMIT() asm volatile("cp.async.commit_group;" ::: "memory")
#define CP_WAIT0()  asm volatile("cp.async.wait_group 0;" ::: "memory")
#define CP_WAIT1()  asm volatile("cp.async.wait_group 1;" ::: "memory")
#define GBAR(id)    asm volatile("bar.sync %0, 128;" :: "r"(id) : "memory")

// ---------------------------------------------------------------------------
// wconv: W fp32 [1024,64] x3 -> hi/lo fp16 [192,1024].
// Wq scaled by 0.125*log2(e) so attention scores are in log2 domain.
// ---------------------------------------------------------------------------
__global__ void wconv_kernel(const float* __restrict__ Wq,
                             const float* __restrict__ Wk,
                             const float* __restrict__ Wv)
{
    int i = blockIdx.x * 256 + threadIdx.x;
    if (i >= NTOT * DD) return;
    int n = i / DD, k = i - n * DD;
    int t = n >> 6, h = n & 63;
    const float* W = (t == 0) ? Wq : ((t == 1) ? Wk : Wv);
    float v = W[(size_t)k * HH + h] * ((t == 0) ? 0.125f * 1.4426950408889634f : 1.0f);
    __half hi = __float2half(v);
    g_wh16[i] = hi;
    g_wl16[i] = __float2half(v - __half2float(hi));
}

// ---------------------------------------------------------------------------
// QKV GEMM: C = x * W^T via 2-term fp16 HMMA (x fp16, W = wh+wl).
// KC=32, 3-stage ring (prefetch distance 2, wait_group 1) so cp.async latency
// is covered by a full iteration. 3 x 35840B = 105KB -> 2 CTAs resident/SM.
// Epilogue: Q -> fp16 single; K -> fp16 hi/lo; V -> fp16.
// ---------------------------------------------------------------------------
#define G_STG   35840
#define G_A     0
#define G_BH    5120
#define G_BL    20480
#define G_NC    32

__global__ __launch_bounds__(256, 2) void qkv_mma_kernel(const float* __restrict__ x)
{
    extern __shared__ char smem[];
    const uint32_t sm0 = smem_u32(smem);
    const int tid = threadIdx.x;
    const int wid = tid >> 5, lane = tid & 31;
    const int wm = wid & 1, wn = wid >> 1;
    const int m0 = blockIdx.x * 64;

    const int li  = lane & 7;
    const int r16 = lane & 15;
    const int hfA = (lane >> 4) * 16;
    const int nh8 = ((lane >> 4) & 1) * 8;
    const int kh16 = ((lane >> 3) & 1) * 16;

    float acc[2][6][4];
    #pragma unroll
    for (int mi = 0; mi < 2; ++mi)
        #pragma unroll
        for (int j = 0; j < 6; ++j)
            #pragma unroll
            for (int q = 0; q < 4; ++q) acc[mi][j][q] = 0.0f;

    const int ar   = tid >> 2;          // A row 0..63
    const int ac0e = (tid & 3) * 8;     // A element offset 0,8,16,24

    // ---- prologue: fill stages 0 and 1 (chunks 0, 1) ----
    #pragma unroll
    for (int cc = 0; cc < 2; ++cc) {
        const float* ap = x + (size_t)(m0 + ar) * DD + cc * 32 + ac0e;
        float4 a0 = *(const float4*)ap;
        float4 a1 = *(const float4*)(ap + 4);
        const uint32_t ob = sm0 + cc * G_STG;
        #pragma unroll
        for (int i = 0; i < 3; ++i) {                  // 768 x 16B per array
            int id = tid + 256 * i, row = id >> 2, ch = id & 3;
            CP_ASYNC16(ob + G_BH + row * 80 + ch * 16,
                       g_wh16 + (size_t)row * DD + cc * 32 + ch * 8);
            CP_ASYNC16(ob + G_BL + row * 80 + ch * 16,
                       g_wl16 + (size_t)row * DD + cc * 32 + ch * 8);
        }
        CP_COMMIT();
        uint4 hv;
        hv.x = pack_h2(a0.x, a0.y);
        hv.y = pack_h2(a0.z, a0.w);
        hv.z = pack_h2(a1.x, a1.y);
        hv.w = pack_h2(a1.z, a1.w);
        *(uint4*)(smem + cc * G_STG + G_A + ar * 80 + ac0e * 2) = hv;
    }
    CP_WAIT1();          // stage 0's B ready (stage 1 may still be in flight)
    __syncthreads();

    for (int c = 0; c < G_NC; ++c) {
        const uint32_t sb = sm0 + (c % 3) * G_STG;

        float4 a0, a1;
        uint32_t ob = 0;
        const bool pf = (c + 2 < G_NC);
        if (pf) {   // prefetch chunk c+2 into stage (c+2)%3
            const float* ap = x + (size_t)(m0 + ar) * DD + (c + 2) * 32 + ac0e;
            a0 = *(const float4*)ap;
            a1 = *(const float4*)(ap + 4);
            ob = sm0 + ((c + 2) % 3) * G_STG;
            #pragma unroll
            for (int i = 0; i < 3; ++i) {
                int id = tid + 256 * i, row = id >> 2, ch = id & 3;
                CP_ASYNC16(ob + G_BH + row * 80 + ch * 16,
                           g_wh16 + (size_t)row * DD + (c + 2) * 32 + ch * 8);
                CP_ASYNC16(ob + G_BL + row * 80 + ch * 16,
                           g_wl16 + (size_t)row * DD + (c + 2) * 32 + ch * 8);
            }
            CP_COMMIT();
        }

        // ---- consume stage c%3: 2 k16-steps ----
        #pragma unroll
        for (int kk = 0; kk < 2; ++kk) {
            uint32_t Af[2][4];
            #pragma unroll
            for (int mi = 0; mi < 2; ++mi) {
                uint32_t a = sb + G_A + (wm * 32 + mi * 16 + r16) * 80 + kk * 32 + hfA;
                ldsm_x4(Af[mi], a);
            }
            uint32_t Bh[6][2], Bl[6][2];
            #pragma unroll
            for (int j2 = 0; j2 < 3; ++j2) {
                uint32_t a = sb + (wn * 48 + j2 * 16 + li + nh8) * 80 + kk * 32 + kh16;
                ldsm_x4(&Bh[2 * j2][0], a + G_BH);
                ldsm_x4(&Bl[2 * j2][0], a + G_BL);
            }
            #pragma unroll
            for (int mi = 0; mi < 2; ++mi)
                #pragma unroll
                for (int j = 0; j < 6; ++j) {
                    mma_f16(acc[mi][j], Af[mi], Bh[j]);
                    mma_f16(acc[mi][j], Af[mi], Bl[j]);
                }
        }

        if (pf) {   // store converted A for chunk c+2
            uint4 hv;
            hv.x = pack_h2(a0.x, a0.y);
            hv.y = pack_h2(a0.z, a0.w);
            hv.z = pack_h2(a1.x, a1.y);
            hv.w = pack_h2(a1.z, a1.w);
            *(uint4*)((char*)smem + (ob - sm0) + G_A + ar * 80 + ac0e * 2) = hv;
        }
        // ensure chunk c+1's B has landed; the c+2 prefetch may stay in flight
        if (pf) CP_WAIT1(); else CP_WAIT0();
        __syncthreads();
    }

    // ---- epilogue: Q -> fp16; K -> fp16 hi/lo; V -> fp16 ----
    const int g = lane >> 2, t2 = (lane & 3) * 2;
    #pragma unroll
    for (int mi = 0; mi < 2; ++mi) {
        #pragma unroll
        for (int j = 0; j < 6; ++j) {
            const int nG = wn * 48 + j * 8 + t2;
            const int tns = nG >> 6, h = nG & 63;
            const int rowA = m0 + wm * 32 + mi * 16 + g;
            if (tns == 0) {
                *(uint32_t*)&g_Q16[(size_t)rowA * HH + h] =
                    pack_h2(acc[mi][j][0], acc[mi][j][1]);
                *(uint32_t*)&g_Q16[(size_t)(rowA + 8) * HH + h] =
                    pack_h2(acc[mi][j][2], acc[mi][j][3]);
            } else if (tns == 2) {
                *(uint32_t*)&g_V16[(size_t)rowA * HH + h] =
                    pack_h2(acc[mi][j][0], acc[mi][j][1]);
                *(uint32_t*)&g_V16[(size_t)(rowA + 8) * HH + h] =
                    pack_h2(acc[mi][j][2], acc[mi][j][3]);
            } else {
                uint32_t hi, lo;
                split2h(acc[mi][j][0], acc[mi][j][1], hi, lo);
                *(uint32_t*)&g_K16h[(size_t)rowA * HH + h] = hi;
                *(uint32_t*)&g_K16l[(size_t)rowA * HH + h] = lo;
                split2h(acc[mi][j][2], acc[mi][j][3], hi, lo);
                *(uint32_t*)&g_K16h[(size_t)(rowA + 8) * HH + h] = hi;
                *(uint32_t*)&g_K16l[(size_t)(rowA + 8) * HH + h] = lo;
            }
        }
    }
}

// ---------------------------------------------------------------------------
// Attention: causal flash, split-KV across two 4-warp groups (256 threads).
// QK = 2-term fp16; softmax via ex2.f16x2; row-sums (l) via mma against a
// ones B-fragment (replaces 16 cvt + 16 add + 4 shfl); PV = 1-term fp16.
// grid (32,4): CTA handles q-blocks {p, 63-p}; group g does kb ≡ g (mod 2).
// ---------------------------------------------------------------------------
#define A_Q   0
#define A_ST0 9216       // 4 stages (2 per group); per stage: Kh | Kl | V (fp16)
#define A_STG 27648
#define A_KH 0
#define A_KL 9216
#define A_V  18432
#define A_SMEM (A_ST0 + 4 * A_STG)    // 119808

__global__ __launch_bounds__(256, 1) void attn_mma_kernel(float* __restrict__ out)
{
    extern __shared__ char smem[];
    const uint32_t sm0 = smem_u32(smem);
    const int b = blockIdx.y, pid = blockIdx.x;
    const int tid = threadIdx.x;
    const int w = tid >> 5, lane = tid & 31;
    const int grp = w >> 2, wg = w & 3;      // group 0/1, warp-in-group 0..3
    const int gtid = tid & 127;              // thread id within group

    const int li   = lane & 7;
    const int r16  = lane & 15;
    const int hfA  = (lane >> 4) * 16;
    const int nh8  = ((lane >> 4) & 1) * 8;
    const int kh16 = ((lane >> 3) & 1) * 16;
    const int sh8  = ((lane >> 3) & 1) * 8;
    const int hh16 = ((lane >> 4) & 1) * 16;
    const int g = lane >> 2, t2 = (lane & 3) * 2;

    const uint32_t ones2[2] = {0x3C003C00u, 0x3C003C00u};   // fp16 1.0 x2

    const size_t base = (size_t)b * SS * HH;

    for (int pass = 0; pass < 2; ++pass) {
        const int qb = pass ? (63 - pid) : pid;
        const int ng = (qb >= grp) ? (((qb - grp) >> 1) + 1) : 0;

        // prefetch this group's first tile (kb = grp) into its stage 0
        if (ng > 0) {
            const uint32_t ob = sm0 + A_ST0 + (2 * grp) * A_STG;
            const size_t kvo = base + (size_t)grp * 64 * HH;
            #pragma unroll
            for (int i = 0; i < 12; ++i) {
                int id = gtid + 128 * i;
                int arr = id >> 9, rem = id & 511, row = rem >> 3, ch = rem & 7;
                const __half* src = (arr == 0) ? g_K16h : (arr == 1) ? g_K16l : g_V16;
                CP_ASYNC16(ob + arr * 9216 + row * 144 + ch * 16,
                           src + kvo + (size_t)row * HH + ch * 8);
            }
        }
        CP_COMMIT();
        // load Q tile fp16 (all 256 threads; 512 chunks)
        {
            const size_t qo = base + (size_t)qb * 64 * HH;
            #pragma unroll
            for (int i = 0; i < 2; ++i) {
                int id = tid + 256 * i;
                int row = id >> 3, ch = id & 7;
                *(uint4*)(smem + A_Q + row * 144 + ch * 16) =
                    *(const uint4*)(g_Q16 + qo + (size_t)row * HH + ch * 8);
            }
        }
        CP_WAIT0();
        __syncthreads();

        uint32_t q16[4][4];
        #pragma unroll
        for (int kk = 0; kk < 4; ++kk) {
            uint32_t a = sm0 + A_Q + (wg * 16 + r16) * 144 + kk * 32 + hfA;
            ldsm_x4(q16[kk], a);
        }

        float O[8][4];
        float m_[2] = {-1e30f, -1e30f}, l_[2] = {0.0f, 0.0f};
        #pragma unroll
        for (int j = 0; j < 8; ++j)
            #pragma unroll
            for (int q = 0; q < 4; ++q) O[j][q] = 0.0f;

        for (int t = 0; t < ng; ++t) {
            const int kb = grp + 2 * t;
            const int s = t & 1;
            const uint32_t sb = sm0 + A_ST0 + (2 * grp + s) * A_STG;

            if (t + 1 < ng) {     // prefetch this group's next tile (kb+2)
                const uint32_t ob = sm0 + A_ST0 + (2 * grp + (s ^ 1)) * A_STG;
                const size_t kvo = base + (size_t)(kb + 2) * 64 * HH;
                #pragma unroll
                for (int i = 0; i < 12; ++i) {
                    int id = gtid + 128 * i;
                    int arr = id >> 9, rem = id & 511, row = rem >> 3, ch = rem & 7;
                    const __half* src = (arr == 0) ? g_K16h : (arr == 1) ? g_K16l : g_V16;
                    CP_ASYNC16(ob + arr * 9216 + row * 144 + ch * 16,
                               src + kvo + (size_t)row * HH + ch * 8);
                }
                CP_COMMIT();
            }

            // ---- S = q16 (Kh + Kl)^T, 2 terms (log2-domain) ----
            float S[8][4];
            #pragma unroll
            for (int j = 0; j < 8; ++j)
                #pragma unroll
                for (int q = 0; q < 4; ++q) S[j][q] = 0.0f;

            #pragma unroll
            for (int kk = 0; kk < 4; ++kk) {
                uint32_t Kh[8][2], Kl[8][2];
                #pragma unroll
                for (int n2 = 0; n2 < 4; ++n2) {
                    uint32_t a = sb + (n2 * 16 + li + nh8) * 144 + kk * 32 + kh16;
                    ldsm_x4(&Kh[2 * n2][0], a + A_KH);
                    ldsm_x4(&Kl[2 * n2][0], a + A_KL);
                }
                #pragma unroll
                for (int j = 0; j < 8; ++j) {
                    mma_f16(S[j], q16[kk], Kh[j]);
                    mma_f16(S[j], q16[kk], Kl[j]);
                }
            }

            if (kb == qb) {       // diagonal tile: causal mask (local coords)
                const int rA = wg * 16 + g, rB = rA + 8;
                #pragma unroll
                for (int j = 0; j < 8; ++j) {
                    const int c0 = j * 8 + t2;
                    if (c0 > rA)     S[j][0] = -1e30f;
                    if (c0 + 1 > rA) S[j][1] = -1e30f;
                    if (c0 > rB)     S[j][2] = -1e30f;
                    if (c0 + 1 > rB) S[j][3] = -1e30f;
                }
            }

            // ---- online softmax, exp2 domain; P emitted as fp16x2 frags ----
            float mx0 = fmaxf(S[0][0], S[0][1]);
            float mx1 = fmaxf(S[0][2], S[0][3]);
            #pragma unroll
            for (int j = 1; j < 8; ++j) {
                mx0 = fmaxf(mx0, fmaxf(S[j][0], S[j][1]));
                mx1 = fmaxf(mx1, fmaxf(S[j][2], S[j][3]));
            }
            mx0 = fmaxf(mx0, __shfl_xor_sync(0xffffffffu, mx0, 1));
            mx0 = fmaxf(mx0, __shfl_xor_sync(0xffffffffu, mx0, 2));
            mx1 = fmaxf(mx1, __shfl_xor_sync(0xffffffffu, mx1, 1));
            mx1 = fmaxf(mx1, __shfl_xor_sync(0xffffffffu, mx1, 2));
            const float mn0 = fmaxf(m_[0], mx0);
            const float mn1 = fmaxf(m_[1], mx1);
            const float corr0 = ex2f(m_[0] - mn0);
            const float corr1 = ex2f(m_[1] - mn1);
            m_[0] = mn0; m_[1] = mn1;

            uint32_t EA[8], EB[8];
            #pragma unroll
            for (int j = 0; j < 8; ++j) {
                EA[j] = ex2_h2(pack_h2(S[j][0] - mn0, S[j][1] - mn0));
                EB[j] = ex2_h2(pack_h2(S[j][2] - mn1, S[j][3] - mn1));
            }
            #pragma unroll
            for (int j = 0; j < 8; ++j) {
                O[j][0] *= corr0; O[j][1] *= corr0;
                O[j][2] *= corr1; O[j][3] *= corr1;
            }

            // ---- O += P V (1-term fp16); l row-sums via ones-fragment mma ----
            float L[4] = {0.0f, 0.0f, 0.0f, 0.0f};
            #pragma unroll
            for (int kk = 0; kk < 4; ++kk) {
                uint32_t p[4] = {EA[2 * kk], EB[2 * kk], EA[2 * kk + 1], EB[2 * kk + 1]};
                mma_f16(L, p, ones2);       // row-sums of this k16 slice of P
                uint32_t Vf[8][2];
                #pragma unroll
                for (int h2 = 0; h2 < 4; ++h2) {
                    uint32_t a = sb + A_V + (kk * 16 + li + sh8) * 144 + h2 * 32 + hh16;
                    ldsm_x4_t(&Vf[2 * h2][0], a);
                }
                #pragma unroll
                for (int j = 0; j < 8; ++j)
                    mma_f16(O[j], p, Vf[j]);
            }
            l_[0] = l_[0] * corr0 + L[0];
            l_[1] = l_[1] * corr1 + L[2];

            CP_WAIT0();
            GBAR(1 + grp);       // group-local barrier (stages are per-group)
        }

        // ---- merge partials: group1 -> smem, group0 combines + writes ----
        __syncthreads();         // all tiles done; stage smem reusable
        float* mb = (float*)(smem + A_ST0);
        if (grp == 1) {
            float* slot = mb + gtid * 36;
            #pragma unroll
            for (int j = 0; j < 8; ++j)
                #pragma unroll
                for (int q = 0; q < 4; ++q) slot[j * 4 + q] = O[j][q];
            slot[32] = m_[0]; slot[33] = m_[1];
            slot[34] = l_[0]; slot[35] = l_[1];
        }
        __syncthreads();
        if (grp == 0) {
            const float* slot = mb + gtid * 36;
            const float m1a = slot[32], m1b = slot[33];
            const float l1a = slot[34], l1b = slot[35];
            const float mnA = fmaxf(m_[0], m1a), mnB = fmaxf(m_[1], m1b);
            const float c00 = ex2f(m_[0] - mnA), c01 = ex2f(m1a - mnA);
            const float c10 = ex2f(m_[1] - mnB), c11 = ex2f(m1b - mnB);
            const float iA = 1.0f / (l_[0] * c00 + l1a * c01);
            const float iB = 1.0f / (l_[1] * c10 + l1b * c11);
            const int rowA = qb * 64 + wg * 16 + g;
            float* ob = out + (size_t)b * SS * HH;
            #pragma unroll
            for (int j = 0; j < 8; ++j) {
                const int col = j * 8 + t2;
                float2 v0, v1;
                v0.x = (O[j][0] * c00 + slot[j * 4 + 0] * c01) * iA;
                v0.y = (O[j][1] * c00 + slot[j * 4 + 1] * c01) * iA;
                v1.x = (O[j][2] * c10 + slot[j * 4 + 2] * c11) * iB;
                v1.y = (O[j][3] * c10 + slot[j * 4 + 3] * c11) * iB;
                *(float2*)&ob[(size_t)rowA * HH + col] = v0;
                *(float2*)&ob[(size_t)(rowA + 8) * HH + col] = v1;
            }
        }
        __syncthreads();         // before next pass overwrites Q smem / stages
    }
}

// ---------------------------------------------------------------------------
extern "C" void kernel_launch(void* const* d_in, const int* in_sizes, int n_in,
                              void* d_out, int out_size)
{
    (void)in_sizes; (void)n_in; (void)out_size;
    const float* x  = (const float*)d_in[0];
    const float* Wq = (const float*)d_in[1];
    const float* Wk = (const float*)d_in[2];
    const float* Wv = (const float*)d_in[3];
    float* out = (float*)d_out;

    static int attr_set = 0;
    const int gemm_smem = 3 * G_STG;                // 107520 -> 2 CTAs/SM
    const int attn_smem = A_SMEM;                   // 119808
    if (!attr_set) {
        cudaFuncSetAttribute(qkv_mma_kernel,
                             cudaFuncAttributeMaxDynamicSharedMemorySize, gemm_smem);
        cudaFuncSetAttribute(attn_mma_kernel,
                             cudaFuncAttributeMaxDynamicSharedMemorySize, attn_smem);
        attr_set = 1;
    }

    wconv_kernel<<<(NTOT * DD + 255) / 256, 256>>>(Wq, Wk, Wv);
    qkv_mma_kernel<<<SS * BB / 64, 256, gemm_smem>>>(x);
    attn_mma_kernel<<<dim3(32, 4), 256, attn_smem>>>(out);
}

// round 16
// speedup vs baseline: 1.2973x; 1.1177x over previous
#include <cuda_runtime.h>
#include <cuda_bf16.h>
#include <cuda_fp16.h>
#include <cstdint>

#define BB 4
#define SS 4096
#define DD 1024
#define HH 64
#define NTOT 192

// Attention operands: Q, K, V all single fp16 (Q carries 0.125*log2e).
__device__ __half g_Q16[BB * SS * HH];
__device__ __half g_K16[BB * SS * HH];
__device__ __half g_V16[BB * SS * HH];
// W fp16 hi/lo, transposed to [N=192][K=1024]; Wq pre-scaled by 0.125*log2(e)
__device__ __half g_wh16[NTOT * DD];
__device__ __half g_wl16[NTOT * DD];

// ---------------------------------------------------------------------------
// Stable-PTX helpers (harness emits compute_103 PTX: no tcgen05 allowed)
// ---------------------------------------------------------------------------
__device__ __forceinline__ uint32_t smem_u32(const void* p) {
    uint32_t a;
    asm("{ .reg .u64 t; cvta.to.shared.u64 t, %1; cvt.u32.u64 %0, t; }" : "=r"(a) : "l"(p));
    return a;
}
__device__ __forceinline__ void mma_f16(float* c, const uint32_t* a, const uint32_t* b) {
    asm volatile(
        "mma.sync.aligned.m16n8k16.row.col.f32.f16.f16.f32 "
        "{%0,%1,%2,%3}, {%4,%5,%6,%7}, {%8,%9}, {%0,%1,%2,%3};"
        : "+f"(c[0]), "+f"(c[1]), "+f"(c[2]), "+f"(c[3])
        : "r"(a[0]), "r"(a[1]), "r"(a[2]), "r"(a[3]), "r"(b[0]), "r"(b[1]));
}
__device__ __forceinline__ void ldsm_x4(uint32_t* r, uint32_t addr) {
    asm volatile("ldmatrix.sync.aligned.m8n8.x4.shared.b16 {%0,%1,%2,%3}, [%4];"
                 : "=r"(r[0]), "=r"(r[1]), "=r"(r[2]), "=r"(r[3]) : "r"(addr));
}
__device__ __forceinline__ void ldsm_x4_t(uint32_t* r, uint32_t addr) {
    asm volatile("ldmatrix.sync.aligned.m8n8.x4.trans.shared.b16 {%0,%1,%2,%3}, [%4];"
                 : "=r"(r[0]), "=r"(r[1]), "=r"(r[2]), "=r"(r[3]) : "r"(addr));
}
__device__ __forceinline__ uint32_t pack_h2(float lo, float hi) {   // lo -> low half
    uint32_t r;
    asm("cvt.rn.f16x2.f32 %0, %1, %2;" : "=r"(r) : "f"(hi), "f"(lo));
    return r;
}
__device__ __forceinline__ uint32_t ex2_h2(uint32_t h2) {
    uint32_t r;
    asm("ex2.approx.f16x2 %0, %1;" : "=r"(r) : "r"(h2));
    return r;
}
__device__ __forceinline__ float ex2f(float x) {
    float r;
    asm("ex2.approx.f32 %0, %1;" : "=f"(r) : "f"(x));
    return r;
}
#define CP_ASYNC16(dst, src) \
    asm volatile("cp.async.cg.shared.global [%0], [%1], 16;" :: "r"(dst), "l"(src) : "memory")
#define CP_COMMIT() asm volatile("cp.async.commit_group;" ::: "memory")
#define CP_WAIT0()  asm volatile("cp.async.wait_group 0;" ::: "memory")
#define CP_WAIT1()  asm volatile("cp.async.wait_group 1;" ::: "memory")
#define GBAR(id)    asm volatile("bar.sync %0, 128;" :: "r"(id) : "memory")

// ---------------------------------------------------------------------------
// wconv: W fp32 [1024,64] x3 -> hi/lo fp16 [192,1024].
// Wq scaled by 0.125*log2(e) so attention scores are in log2 domain.
// ---------------------------------------------------------------------------
__global__ void wconv_kernel(const float* __restrict__ Wq,
                             const float* __restrict__ Wk,
                             const float* __restrict__ Wv)
{
    int i = blockIdx.x * 256 + threadIdx.x;
    if (i >= NTOT * DD) return;
    int n = i / DD, k = i - n * DD;
    int t = n >> 6, h = n & 63;
    const float* W = (t == 0) ? Wq : ((t == 1) ? Wk : Wv);
    float v = W[(size_t)k * HH + h] * ((t == 0) ? 0.125f * 1.4426950408889634f : 1.0f);
    __half hi = __float2half(v);
    g_wh16[i] = hi;
    g_wl16[i] = __float2half(v - __half2float(hi));
}

// ---------------------------------------------------------------------------
// QKV GEMM: C = x * W^T via 2-term fp16 HMMA (x fp16, W = wh+wl).
// KC=32, 3-stage ring (prefetch distance 2, wait_group 1). 2 CTAs/SM.
// Epilogue: Q, K, V all -> single fp16.
// ---------------------------------------------------------------------------
#define G_STG   35840
#define G_A     0
#define G_BH    5120
#define G_BL    20480
#define G_NC    32

__global__ __launch_bounds__(256, 2) void qkv_mma_kernel(const float* __restrict__ x)
{
    extern __shared__ char smem[];
    const uint32_t sm0 = smem_u32(smem);
    const int tid = threadIdx.x;
    const int wid = tid >> 5, lane = tid & 31;
    const int wm = wid & 1, wn = wid >> 1;
    const int m0 = blockIdx.x * 64;

    const int li  = lane & 7;
    const int r16 = lane & 15;
    const int hfA = (lane >> 4) * 16;
    const int nh8 = ((lane >> 4) & 1) * 8;
    const int kh16 = ((lane >> 3) & 1) * 16;

    float acc[2][6][4];
    #pragma unroll
    for (int mi = 0; mi < 2; ++mi)
        #pragma unroll
        for (int j = 0; j < 6; ++j)
            #pragma unroll
            for (int q = 0; q < 4; ++q) acc[mi][j][q] = 0.0f;

    const int ar   = tid >> 2;          // A row 0..63
    const int ac0e = (tid & 3) * 8;     // A element offset 0,8,16,24

    // ---- prologue: fill stages 0 and 1 (chunks 0, 1) ----
    #pragma unroll
    for (int cc = 0; cc < 2; ++cc) {
        const float* ap = x + (size_t)(m0 + ar) * DD + cc * 32 + ac0e;
        float4 a0 = *(const float4*)ap;
        float4 a1 = *(const float4*)(ap + 4);
        const uint32_t ob = sm0 + cc * G_STG;
        #pragma unroll
        for (int i = 0; i < 3; ++i) {                  // 768 x 16B per array
            int id = tid + 256 * i, row = id >> 2, ch = id & 3;
            CP_ASYNC16(ob + G_BH + row * 80 + ch * 16,
                       g_wh16 + (size_t)row * DD + cc * 32 + ch * 8);
            CP_ASYNC16(ob + G_BL + row * 80 + ch * 16,
                       g_wl16 + (size_t)row * DD + cc * 32 + ch * 8);
        }
        CP_COMMIT();
        uint4 hv;
        hv.x = pack_h2(a0.x, a0.y);
        hv.y = pack_h2(a0.z, a0.w);
        hv.z = pack_h2(a1.x, a1.y);
        hv.w = pack_h2(a1.z, a1.w);
        *(uint4*)(smem + cc * G_STG + G_A + ar * 80 + ac0e * 2) = hv;
    }
    CP_WAIT1();          // stage 0's B ready (stage 1 may still be in flight)
    __syncthreads();

    for (int c = 0; c < G_NC; ++c) {
        const uint32_t sb = sm0 + (c % 3) * G_STG;

        float4 a0, a1;
        uint32_t ob = 0;
        const bool pf = (c + 2 < G_NC);
        if (pf) {   // prefetch chunk c+2 into stage (c+2)%3
            const float* ap = x + (size_t)(m0 + ar) * DD + (c + 2) * 32 + ac0e;
            a0 = *(const float4*)ap;
            a1 = *(const float4*)(ap + 4);
            ob = sm0 + ((c + 2) % 3) * G_STG;
            #pragma unroll
            for (int i = 0; i < 3; ++i) {
                int id = tid + 256 * i, row = id >> 2, ch = id & 3;
                CP_ASYNC16(ob + G_BH + row * 80 + ch * 16,
                           g_wh16 + (size_t)row * DD + (c + 2) * 32 + ch * 8);
                CP_ASYNC16(ob + G_BL + row * 80 + ch * 16,
                           g_wl16 + (size_t)row * DD + (c + 2) * 32 + ch * 8);
            }
            CP_COMMIT();
        }

        // ---- consume stage c%3: 2 k16-steps ----
        #pragma unroll
        for (int kk = 0; kk < 2; ++kk) {
            uint32_t Af[2][4];
            #pragma unroll
            for (int mi = 0; mi < 2; ++mi) {
                uint32_t a = sb + G_A + (wm * 32 + mi * 16 + r16) * 80 + kk * 32 + hfA;
                ldsm_x4(Af[mi], a);
            }
            uint32_t Bh[6][2], Bl[6][2];
            #pragma unroll
            for (int j2 = 0; j2 < 3; ++j2) {
                uint32_t a = sb + (wn * 48 + j2 * 16 + li + nh8) * 80 + kk * 32 + kh16;
                ldsm_x4(&Bh[2 * j2][0], a + G_BH);
                ldsm_x4(&Bl[2 * j2][0], a + G_BL);
            }
            #pragma unroll
            for (int mi = 0; mi < 2; ++mi)
                #pragma unroll
                for (int j = 0; j < 6; ++j) {
                    mma_f16(acc[mi][j], Af[mi], Bh[j]);
                    mma_f16(acc[mi][j], Af[mi], Bl[j]);
                }
        }

        if (pf) {   // store converted A for chunk c+2
            uint4 hv;
            hv.x = pack_h2(a0.x, a0.y);
            hv.y = pack_h2(a0.z, a0.w);
            hv.z = pack_h2(a1.x, a1.y);
            hv.w = pack_h2(a1.z, a1.w);
            *(uint4*)((char*)smem + (ob - sm0) + G_A + ar * 80 + ac0e * 2) = hv;
        }
        if (pf) CP_WAIT1(); else CP_WAIT0();
        __syncthreads();
    }

    // ---- epilogue: Q, K, V all single fp16 ----
    const int g = lane >> 2, t2 = (lane & 3) * 2;
    #pragma unroll
    for (int mi = 0; mi < 2; ++mi) {
        #pragma unroll
        for (int j = 0; j < 6; ++j) {
            const int nG = wn * 48 + j * 8 + t2;
            const int tns = nG >> 6, h = nG & 63;
            const int rowA = m0 + wm * 32 + mi * 16 + g;
            __half* op = (tns == 0) ? g_Q16 : ((tns == 1) ? g_K16 : g_V16);
            *(uint32_t*)&op[(size_t)rowA * HH + h] =
                pack_h2(acc[mi][j][0], acc[mi][j][1]);
            *(uint32_t*)&op[(size_t)(rowA + 8) * HH + h] =
                pack_h2(acc[mi][j][2], acc[mi][j][3]);
        }
    }
}

// ---------------------------------------------------------------------------
// Attention: causal flash, split-KV across two 4-warp groups (256 threads).
// QK = 1-term fp16; softmax via ex2.f16x2; l via ones-fragment mma;
// PV = 1-term fp16. Stage = K|V (18432B) -> 83KB smem -> 2 CTAs/SM.
// grid (32,4): CTA handles q-blocks {p, 63-p}; group g does kb ≡ g (mod 2).
// ---------------------------------------------------------------------------
#define A_Q   0
#define A_ST0 9216       // 4 stages (2 per group); per stage: K | V (fp16)
#define A_STG 18432
#define A_K  0
#define A_V  9216
#define A_SMEM (A_ST0 + 4 * A_STG)    // 82944

__global__ __launch_bounds__(256, 2) void attn_mma_kernel(float* __restrict__ out)
{
    extern __shared__ char smem[];
    const uint32_t sm0 = smem_u32(smem);
    const int b = blockIdx.y, pid = blockIdx.x;
    const int tid = threadIdx.x;
    const int w = tid >> 5, lane = tid & 31;
    const int grp = w >> 2, wg = w & 3;      // group 0/1, warp-in-group 0..3
    const int gtid = tid & 127;              // thread id within group

    const int li   = lane & 7;
    const int r16  = lane & 15;
    const int hfA  = (lane >> 4) * 16;
    const int nh8  = ((lane >> 4) & 1) * 8;
    const int kh16 = ((lane >> 3) & 1) * 16;
    const int sh8  = ((lane >> 3) & 1) * 8;
    const int hh16 = ((lane >> 4) & 1) * 16;
    const int g = lane >> 2, t2 = (lane & 3) * 2;

    const uint32_t ones2[2] = {0x3C003C00u, 0x3C003C00u};   // fp16 1.0 x2

    const size_t base = (size_t)b * SS * HH;

    for (int pass = 0; pass < 2; ++pass) {
        const int qb = pass ? (63 - pid) : pid;
        const int ng = (qb >= grp) ? (((qb - grp) >> 1) + 1) : 0;

        // prefetch this group's first tile (kb = grp) into its stage 0
        if (ng > 0) {
            const uint32_t ob = sm0 + A_ST0 + (2 * grp) * A_STG;
            const size_t kvo = base + (size_t)grp * 64 * HH;
            #pragma unroll
            for (int i = 0; i < 8; ++i) {          // 1024 chunks: arr(2) x row(64) x ch(8)
                int id = gtid + 128 * i;
                int arr = id >> 9, rem = id & 511, row = rem >> 3, ch = rem & 7;
                const __half* src = arr ? g_V16 : g_K16;
                CP_ASYNC16(ob + arr * 9216 + row * 144 + ch * 16,
                           src + kvo + (size_t)row * HH + ch * 8);
            }
        }
        CP_COMMIT();
        // load Q tile fp16 (all 256 threads; 512 chunks)
        {
            const size_t qo = base + (size_t)qb * 64 * HH;
            #pragma unroll
            for (int i = 0; i < 2; ++i) {
                int id = tid + 256 * i;
                int row = id >> 3, ch = id & 7;
                *(uint4*)(smem + A_Q + row * 144 + ch * 16) =
                    *(const uint4*)(g_Q16 + qo + (size_t)row * HH + ch * 8);
            }
        }
        CP_WAIT0();
        __syncthreads();

        uint32_t q16[4][4];
        #pragma unroll
        for (int kk = 0; kk < 4; ++kk) {
            uint32_t a = sm0 + A_Q + (wg * 16 + r16) * 144 + kk * 32 + hfA;
            ldsm_x4(q16[kk], a);
        }

        float O[8][4];
        float m_[2] = {-1e30f, -1e30f}, l_[2] = {0.0f, 0.0f};
        #pragma unroll
        for (int j = 0; j < 8; ++j)
            #pragma unroll
            for (int q = 0; q < 4; ++q) O[j][q] = 0.0f;

        for (int t = 0; t < ng; ++t) {
            const int kb = grp + 2 * t;
            const int s = t & 1;
            const uint32_t sb = sm0 + A_ST0 + (2 * grp + s) * A_STG;

            if (t + 1 < ng) {     // prefetch this group's next tile (kb+2)
                const uint32_t ob = sm0 + A_ST0 + (2 * grp + (s ^ 1)) * A_STG;
                const size_t kvo = base + (size_t)(kb + 2) * 64 * HH;
                #pragma unroll
                for (int i = 0; i < 8; ++i) {
                    int id = gtid + 128 * i;
                    int arr = id >> 9, rem = id & 511, row = rem >> 3, ch = rem & 7;
                    const __half* src = arr ? g_V16 : g_K16;
                    CP_ASYNC16(ob + arr * 9216 + row * 144 + ch * 16,
                               src + kvo + (size_t)row * HH + ch * 8);
                }
                CP_COMMIT();
            }

            // ---- S = q16 K^T, 1-term fp16 (log2-domain) ----
            float S[8][4];
            #pragma unroll
            for (int j = 0; j < 8; ++j)
                #pragma unroll
                for (int q = 0; q < 4; ++q) S[j][q] = 0.0f;

            #pragma unroll
            for (int kk = 0; kk < 4; ++kk) {
                uint32_t Kf[8][2];
                #pragma unroll
                for (int n2 = 0; n2 < 4; ++n2) {
                    uint32_t a = sb + A_K + (n2 * 16 + li + nh8) * 144 + kk * 32 + kh16;
                    ldsm_x4(&Kf[2 * n2][0], a);
                }
                #pragma unroll
                for (int j = 0; j < 8; ++j)
                    mma_f16(S[j], q16[kk], Kf[j]);
            }

            if (kb == qb) {       // diagonal tile: causal mask (local coords)
                const int rA = wg * 16 + g, rB = rA + 8;
                #pragma unroll
                for (int j = 0; j < 8; ++j) {
                    const int c0 = j * 8 + t2;
                    if (c0 > rA)     S[j][0] = -1e30f;
                    if (c0 + 1 > rA) S[j][1] = -1e30f;
                    if (c0 > rB)     S[j][2] = -1e30f;
                    if (c0 + 1 > rB) S[j][3] = -1e30f;
                }
            }

            // ---- online softmax, exp2 domain; P emitted as fp16x2 frags ----
            float mx0 = fmaxf(S[0][0], S[0][1]);
            float mx1 = fmaxf(S[0][2], S[0][3]);
            #pragma unroll
            for (int j = 1; j < 8; ++j) {
                mx0 = fmaxf(mx0, fmaxf(S[j][0], S[j][1]));
                mx1 = fmaxf(mx1, fmaxf(S[j][2], S[j][3]));
            }
            mx0 = fmaxf(mx0, __shfl_xor_sync(0xffffffffu, mx0, 1));
            mx0 = fmaxf(mx0, __shfl_xor_sync(0xffffffffu, mx0, 2));
            mx1 = fmaxf(mx1, __shfl_xor_sync(0xffffffffu, mx1, 1));
            mx1 = fmaxf(mx1, __shfl_xor_sync(0xffffffffu, mx1, 2));
            const float mn0 = fmaxf(m_[0], mx0);
            const float mn1 = fmaxf(m_[1], mx1);
            const float corr0 = ex2f(m_[0] - mn0);
            const float corr1 = ex2f(m_[1] - mn1);
            m_[0] = mn0; m_[1] = mn1;

            uint32_t EA[8], EB[8];
            #pragma unroll
            for (int j = 0; j < 8; ++j) {
                EA[j] = ex2_h2(pack_h2(S[j][0] - mn0, S[j][1] - mn0));
                EB[j] = ex2_h2(pack_h2(S[j][2] - mn1, S[j][3] - mn1));
            }
            #pragma unroll
            for (int j = 0; j < 8; ++j) {
                O[j][0] *= corr0; O[j][1] *= corr0;
                O[j][2] *= corr1; O[j][3] *= corr1;
            }

            // ---- O += P V (1-term fp16); l row-sums via ones-fragment mma ----
            float L[4] = {0.0f, 0.0f, 0.0f, 0.0f};
            #pragma unroll
            for (int kk = 0; kk < 4; ++kk) {
                uint32_t p[4] = {EA[2 * kk], EB[2 * kk], EA[2 * kk + 1], EB[2 * kk + 1]};
                mma_f16(L, p, ones2);       // row-sums of this k16 slice of P
                uint32_t Vf[8][2];
                #pragma unroll
                for (int h2 = 0; h2 < 4; ++h2) {
                    uint32_t a = sb + A_V + (kk * 16 + li + sh8) * 144 + h2 * 32 + hh16;
                    ldsm_x4_t(&Vf[2 * h2][0], a);
                }
                #pragma unroll
                for (int j = 0; j < 8; ++j)
                    mma_f16(O[j], p, Vf[j]);
            }
            l_[0] = l_[0] * corr0 + L[0];
            l_[1] = l_[1] * corr1 + L[2];

            CP_WAIT0();
            GBAR(1 + grp);       // group-local barrier (stages are per-group)
        }

        // ---- merge partials: group1 -> smem, group0 combines + writes ----
        __syncthreads();         // all tiles done; stage smem reusable
        float* mb = (float*)(smem + A_ST0);
        if (grp == 1) {
            float* slot = mb + gtid * 36;
            #pragma unroll
            for (int j = 0; j < 8; ++j)
                #pragma unroll
                for (int q = 0; q < 4; ++q) slot[j * 4 + q] = O[j][q];
            slot[32] = m_[0]; slot[33] = m_[1];
            slot[34] = l_[0]; slot[35] = l_[1];
        }
        __syncthreads();
        if (grp == 0) {
            const float* slot = mb + gtid * 36;
            const float m1a = slot[32], m1b = slot[33];
            const float l1a = slot[34], l1b = slot[35];
            const float mnA = fmaxf(m_[0], m1a), mnB = fmaxf(m_[1], m1b);
            const float c00 = ex2f(m_[0] - mnA), c01 = ex2f(m1a - mnA);
            const float c10 = ex2f(m_[1] - mnB), c11 = ex2f(m1b - mnB);
            const float iA = 1.0f / (l_[0] * c00 + l1a * c01);
            const float iB = 1.0f / (l_[1] * c10 + l1b * c11);
            const int rowA = qb * 64 + wg * 16 + g;
            float* ob = out + (size_t)b * SS * HH;
            #pragma unroll
            for (int j = 0; j < 8; ++j) {
                const int col = j * 8 + t2;
                float2 v0, v1;
                v0.x = (O[j][0] * c00 + slot[j * 4 + 0] * c01) * iA;
                v0.y = (O[j][1] * c00 + slot[j * 4 + 1] * c01) * iA;
                v1.x = (O[j][2] * c10 + slot[j * 4 + 2] * c11) * iB;
                v1.y = (O[j][3] * c10 + slot[j * 4 + 3] * c11) * iB;
                *(float2*)&ob[(size_t)rowA * HH + col] = v0;
                *(float2*)&ob[(size_t)(rowA + 8) * HH + col] = v1;
            }
        }
        __syncthreads();         // before next pass overwrites Q smem / stages
    }
}

// ---------------------------------------------------------------------------
extern "C" void kernel_launch(void* const* d_in, const int* in_sizes, int n_in,
                              void* d_out, int out_size)
{
    (void)in_sizes; (void)n_in; (void)out_size;
    const float* x  = (const float*)d_in[0];
    const float* Wq = (const float*)d_in[1];
    const float* Wk = (const float*)d_in[2];
    const float* Wv = (const float*)d_in[3];
    float* out = (float*)d_out;

    static int attr_set = 0;
    const int gemm_smem = 3 * G_STG;                // 107520 -> 2 CTAs/SM
    const int attn_smem = A_SMEM;                   // 82944  -> 2 CTAs/SM
    if (!attr_set) {
        cudaFuncSetAttribute(qkv_mma_kernel,
                             cudaFuncAttributeMaxDynamicSharedMemorySize, gemm_smem);
        cudaFuncSetAttribute(attn_mma_kernel,
                             cudaFuncAttributeMaxDynamicSharedMemorySize, attn_smem);
        attr_set = 1;
    }

    wconv_kernel<<<(NTOT * DD + 255) / 256, 256>>>(Wq, Wk, Wv);
    qkv_mma_kernel<<<SS * BB / 64, 256, gemm_smem>>>(x);
    attn_mma_kernel<<<dim3(32, 4), 256, attn_smem>>>(out);
}

// round 17
// speedup vs baseline: 1.5122x; 1.1657x over previous
#include <cuda_runtime.h>
#include <cuda_bf16.h>
#include <cuda_fp16.h>
#include <cstdint>

#define BB 4
#define SS 4096
#define DD 1024
#define HH 64
#define NTOT 192

// Attention operands: Q, K, V all single fp16 (Q carries 0.125*log2e).
__device__ __half g_Q16[BB * SS * HH];
__device__ __half g_K16[BB * SS * HH];
__device__ __half g_V16[BB * SS * HH];
// W fp16, permuted layout [192][1024]: warp wn owns rows [wn*48, wn*48+48):
//   rows +0..31  = Q (wn<2) or K (wn>=2), h = (wn&1)*32 + c   (1-term)
//   rows +32..47 = V, h = wn*16 + (c-32)                      (2-term: + lo)
__device__ __half g_wh16[NTOT * DD];
__device__ __half g_wl16v[HH * DD];    // V lo-term only, indexed by V h

// ---------------------------------------------------------------------------
// Stable-PTX helpers (harness emits compute_103 PTX: no tcgen05 allowed)
// ---------------------------------------------------------------------------
__device__ __forceinline__ uint32_t smem_u32(const void* p) {
    uint32_t a;
    asm("{ .reg .u64 t; cvta.to.shared.u64 t, %1; cvt.u32.u64 %0, t; }" : "=r"(a) : "l"(p));
    return a;
}
__device__ __forceinline__ void mma_f16(float* c, const uint32_t* a, const uint32_t* b) {
    asm volatile(
        "mma.sync.aligned.m16n8k16.row.col.f32.f16.f16.f32 "
        "{%0,%1,%2,%3}, {%4,%5,%6,%7}, {%8,%9}, {%0,%1,%2,%3};"
        : "+f"(c[0]), "+f"(c[1]), "+f"(c[2]), "+f"(c[3])
        : "r"(a[0]), "r"(a[1]), "r"(a[2]), "r"(a[3]), "r"(b[0]), "r"(b[1]));
}
__device__ __forceinline__ void ldsm_x4(uint32_t* r, uint32_t addr) {
    asm volatile("ldmatrix.sync.aligned.m8n8.x4.shared.b16 {%0,%1,%2,%3}, [%4];"
                 : "=r"(r[0]), "=r"(r[1]), "=r"(r[2]), "=r"(r[3]) : "r"(addr));
}
__device__ __forceinline__ void ldsm_x4_t(uint32_t* r, uint32_t addr) {
    asm volatile("ldmatrix.sync.aligned.m8n8.x4.trans.shared.b16 {%0,%1,%2,%3}, [%4];"
                 : "=r"(r[0]), "=r"(r[1]), "=r"(r[2]), "=r"(r[3]) : "r"(addr));
}
__device__ __forceinline__ uint32_t pack_h2(float lo, float hi) {   // lo -> low half
    uint32_t r;
    asm("cvt.rn.f16x2.f32 %0, %1, %2;" : "=r"(r) : "f"(hi), "f"(lo));
    return r;
}
__device__ __forceinline__ uint32_t ex2_h2(uint32_t h2) {
    uint32_t r;
    asm("ex2.approx.f16x2 %0, %1;" : "=r"(r) : "r"(h2));
    return r;
}
__device__ __forceinline__ float ex2f(float x) {
    float r;
    asm("ex2.approx.f32 %0, %1;" : "=f"(r) : "f"(x));
    return r;
}
#define CP_ASYNC16(dst, src) \
    asm volatile("cp.async.cg.shared.global [%0], [%1], 16;" :: "r"(dst), "l"(src) : "memory")
#define CP_COMMIT() asm volatile("cp.async.commit_group;" ::: "memory")
#define CP_WAIT0()  asm volatile("cp.async.wait_group 0;" ::: "memory")
#define CP_WAIT1()  asm volatile("cp.async.wait_group 1;" ::: "memory")
#define GBAR(id)    asm volatile("bar.sync %0, 128;" :: "r"(id) : "memory")

// ---------------------------------------------------------------------------
// wconv: W fp32 -> permuted fp16 [192][1024] + V lo-term [64][1024].
// Wq scaled by 0.125*log2(e) so attention scores are in log2 domain.
// ---------------------------------------------------------------------------
__global__ void wconv_kernel(const float* __restrict__ Wq,
                             const float* __restrict__ Wk,
                             const float* __restrict__ Wv)
{
    int i = blockIdx.x * 256 + threadIdx.x;
    if (i >= NTOT * DD) return;
    int n = i / DD, k = i - n * DD;
    int wn = n / 48, c = n - wn * 48;
    float v;
    int vh = -1;
    if (c < 32) {
        const float* W = (wn < 2) ? Wq : Wk;
        v = W[(size_t)k * HH + (wn & 1) * 32 + c];
        if (wn < 2) v *= 0.125f * 1.4426950408889634f;
    } else {
        vh = wn * 16 + (c - 32);
        v = Wv[(size_t)k * HH + vh];
    }
    __half hi = __float2half(v);
    g_wh16[i] = hi;
    if (vh >= 0) g_wl16v[(size_t)vh * DD + k] = __float2half(v - __half2float(hi));
}

// ---------------------------------------------------------------------------
// QKV GEMM: C = x * W^T. Q,K: 1-term fp16; V: 2-term (wh + wl). Permuted B
// layout balances terms: every warp does 8 mma/kk (4 QK + 2x2 V).
// KC=32, 3-stage ring (prefetch distance 2, wait_group 1). 2 CTAs/SM.
// Epilogue: Q, K, V all -> single fp16 (un-permuted).
// ---------------------------------------------------------------------------
#define G_STG   25600
#define G_A     0
#define G_BH    5120
#define G_BLV   20480
#define G_NC    32

__global__ __launch_bounds__(256, 2) void qkv_mma_kernel(const float* __restrict__ x)
{
    extern __shared__ char smem[];
    const uint32_t sm0 = smem_u32(smem);
    const int tid = threadIdx.x;
    const int wid = tid >> 5, lane = tid & 31;
    const int wm = wid & 1, wn = wid >> 1;
    const int m0 = blockIdx.x * 64;

    const int li  = lane & 7;
    const int r16 = lane & 15;
    const int hfA = (lane >> 4) * 16;
    const int nh8 = ((lane >> 4) & 1) * 8;
    const int kh16 = ((lane >> 3) & 1) * 16;

    float acc[2][6][4];
    #pragma unroll
    for (int mi = 0; mi < 2; ++mi)
        #pragma unroll
        for (int j = 0; j < 6; ++j)
            #pragma unroll
            for (int q = 0; q < 4; ++q) acc[mi][j][q] = 0.0f;

    const int ar   = tid >> 2;          // A row 0..63
    const int ac0e = (tid & 3) * 8;     // A element offset 0,8,16,24

    // loads one chunk's B (wh 768 + wlv 256 sixteen-byte pieces) into stage ob
    auto load_B = [&](uint32_t ob, int cc) {
        #pragma unroll
        for (int i = 0; i < 3; ++i) {
            int id = tid + 256 * i, row = id >> 2, ch = id & 3;
            CP_ASYNC16(ob + G_BH + row * 80 + ch * 16,
                       g_wh16 + (size_t)row * DD + cc * 32 + ch * 8);
        }
        {
            int row = tid >> 2, ch = tid & 3;
            CP_ASYNC16(ob + G_BLV + row * 80 + ch * 16,
                       g_wl16v + (size_t)row * DD + cc * 32 + ch * 8);
        }
    };

    // ---- prologue: fill stages 0 and 1 (chunks 0, 1) ----
    #pragma unroll
    for (int cc = 0; cc < 2; ++cc) {
        const float* ap = x + (size_t)(m0 + ar) * DD + cc * 32 + ac0e;
        float4 a0 = *(const float4*)ap;
        float4 a1 = *(const float4*)(ap + 4);
        load_B(sm0 + cc * G_STG, cc);
        CP_COMMIT();
        uint4 hv;
        hv.x = pack_h2(a0.x, a0.y);
        hv.y = pack_h2(a0.z, a0.w);
        hv.z = pack_h2(a1.x, a1.y);
        hv.w = pack_h2(a1.z, a1.w);
        *(uint4*)(smem + cc * G_STG + G_A + ar * 80 + ac0e * 2) = hv;
    }
    CP_WAIT1();
    __syncthreads();

    for (int c = 0; c < G_NC; ++c) {
        const uint32_t sb = sm0 + (c % 3) * G_STG;

        float4 a0, a1;
        uint32_t ob = 0;
        const bool pf = (c + 2 < G_NC);
        if (pf) {   // prefetch chunk c+2 into stage (c+2)%3
            const float* ap = x + (size_t)(m0 + ar) * DD + (c + 2) * 32 + ac0e;
            a0 = *(const float4*)ap;
            a1 = *(const float4*)(ap + 4);
            ob = sm0 + ((c + 2) % 3) * G_STG;
            load_B(ob, c + 2);
            CP_COMMIT();
        }

        // ---- consume stage c%3: 2 k16-steps ----
        #pragma unroll
        for (int kk = 0; kk < 2; ++kk) {
            uint32_t Af[2][4];
            #pragma unroll
            for (int mi = 0; mi < 2; ++mi) {
                uint32_t a = sb + G_A + (wm * 32 + mi * 16 + r16) * 80 + kk * 32 + hfA;
                ldsm_x4(Af[mi], a);
            }
            uint32_t Bh[6][2], Blv[2][2];
            #pragma unroll
            for (int j2 = 0; j2 < 3; ++j2) {
                uint32_t a = sb + G_BH + (wn * 48 + j2 * 16 + li + nh8) * 80 + kk * 32 + kh16;
                ldsm_x4(&Bh[2 * j2][0], a);
            }
            {
                uint32_t a = sb + G_BLV + (wn * 16 + li + nh8) * 80 + kk * 32 + kh16;
                ldsm_x4(&Blv[0][0], a);
            }
            #pragma unroll
            for (int mi = 0; mi < 2; ++mi) {
                #pragma unroll
                for (int j = 0; j < 4; ++j)          // Q/K cols: 1-term
                    mma_f16(acc[mi][j], Af[mi], Bh[j]);
                #pragma unroll
                for (int j = 4; j < 6; ++j) {        // V cols: 2-term
                    mma_f16(acc[mi][j], Af[mi], Bh[j]);
                    mma_f16(acc[mi][j], Af[mi], Blv[j - 4]);
                }
            }
        }

        if (pf) {   // store converted A for chunk c+2
            uint4 hv;
            hv.x = pack_h2(a0.x, a0.y);
            hv.y = pack_h2(a0.z, a0.w);
            hv.z = pack_h2(a1.x, a1.y);
            hv.w = pack_h2(a1.z, a1.w);
            *(uint4*)((char*)smem + (ob - sm0) + G_A + ar * 80 + ac0e * 2) = hv;
        }
        if (pf) CP_WAIT1(); else CP_WAIT0();
        __syncthreads();
    }

    // ---- epilogue: un-permute; Q, K, V all single fp16 ----
    const int g = lane >> 2, t2 = (lane & 3) * 2;
    #pragma unroll
    for (int mi = 0; mi < 2; ++mi) {
        #pragma unroll
        for (int j = 0; j < 6; ++j) {
            const int rowA = m0 + wm * 32 + mi * 16 + g;
            __half* op;
            int h;
            if (j < 4) {                    // Q/K block
                op = (wn < 2) ? g_Q16 : g_K16;
                h = (wn & 1) * 32 + j * 8 + t2;
            } else {                        // V block
                op = g_V16;
                h = wn * 16 + (j - 4) * 8 + t2;
            }
            *(uint32_t*)&op[(size_t)rowA * HH + h] =
                pack_h2(acc[mi][j][0], acc[mi][j][1]);
            *(uint32_t*)&op[(size_t)(rowA + 8) * HH + h] =
                pack_h2(acc[mi][j][2], acc[mi][j][3]);
        }
    }
}

// ---------------------------------------------------------------------------
// Attention (unchanged): causal flash, split-KV across two 4-warp groups.
// QK = 1-term fp16; softmax via ex2.f16x2; l via ones-fragment mma;
// PV = 1-term fp16. Stage = K|V (18432B) -> 83KB smem -> 2 CTAs/SM.
// grid (32,4): CTA handles q-blocks {p, 63-p}; group g does kb ≡ g (mod 2).
// ---------------------------------------------------------------------------
#define A_Q   0
#define A_ST0 9216       // 4 stages (2 per group); per stage: K | V (fp16)
#define A_STG 18432
#define A_K  0
#define A_V  9216
#define A_SMEM (A_ST0 + 4 * A_STG)    // 82944

__global__ __launch_bounds__(256, 2) void attn_mma_kernel(float* __restrict__ out)
{
    extern __shared__ char smem[];
    const uint32_t sm0 = smem_u32(smem);
    const int b = blockIdx.y, pid = blockIdx.x;
    const int tid = threadIdx.x;
    const int w = tid >> 5, lane = tid & 31;
    const int grp = w >> 2, wg = w & 3;      // group 0/1, warp-in-group 0..3
    const int gtid = tid & 127;              // thread id within group

    const int li   = lane & 7;
    const int r16  = lane & 15;
    const int hfA  = (lane >> 4) * 16;
    const int nh8  = ((lane >> 4) & 1) * 8;
    const int kh16 = ((lane >> 3) & 1) * 16;
    const int sh8  = ((lane >> 3) & 1) * 8;
    const int hh16 = ((lane >> 4) & 1) * 16;
    const int g = lane >> 2, t2 = (lane & 3) * 2;

    const uint32_t ones2[2] = {0x3C003C00u, 0x3C003C00u};   // fp16 1.0 x2

    const size_t base = (size_t)b * SS * HH;

    for (int pass = 0; pass < 2; ++pass) {
        const int qb = pass ? (63 - pid) : pid;
        const int ng = (qb >= grp) ? (((qb - grp) >> 1) + 1) : 0;

        // prefetch this group's first tile (kb = grp) into its stage 0
        if (ng > 0) {
            const uint32_t ob = sm0 + A_ST0 + (2 * grp) * A_STG;
            const size_t kvo = base + (size_t)grp * 64 * HH;
            #pragma unroll
            for (int i = 0; i < 8; ++i) {          // 1024 chunks: arr(2) x row(64) x ch(8)
                int id = gtid + 128 * i;
                int arr = id >> 9, rem = id & 511, row = rem >> 3, ch = rem & 7;
                const __half* src = arr ? g_V16 : g_K16;
                CP_ASYNC16(ob + arr * 9216 + row * 144 + ch * 16,
                           src + kvo + (size_t)row * HH + ch * 8);
            }
        }
        CP_COMMIT();
        // load Q tile fp16 (all 256 threads; 512 chunks)
        {
            const size_t qo = base + (size_t)qb * 64 * HH;
            #pragma unroll
            for (int i = 0; i < 2; ++i) {
                int id = tid + 256 * i;
                int row = id >> 3, ch = id & 7;
                *(uint4*)(smem + A_Q + row * 144 + ch * 16) =
                    *(const uint4*)(g_Q16 + qo + (size_t)row * HH + ch * 8);
            }
        }
        CP_WAIT0();
        __syncthreads();

        uint32_t q16[4][4];
        #pragma unroll
        for (int kk = 0; kk < 4; ++kk) {
            uint32_t a = sm0 + A_Q + (wg * 16 + r16) * 144 + kk * 32 + hfA;
            ldsm_x4(q16[kk], a);
        }

        float O[8][4];
        float m_[2] = {-1e30f, -1e30f}, l_[2] = {0.0f, 0.0f};
        #pragma unroll
        for (int j = 0; j < 8; ++j)
            #pragma unroll
            for (int q = 0; q < 4; ++q) O[j][q] = 0.0f;

        for (int t = 0; t < ng; ++t) {
            const int kb = grp + 2 * t;
            const int s = t & 1;
            const uint32_t sb = sm0 + A_ST0 + (2 * grp + s) * A_STG;

            if (t + 1 < ng) {     // prefetch this group's next tile (kb+2)
                const uint32_t ob = sm0 + A_ST0 + (2 * grp + (s ^ 1)) * A_STG;
                const size_t kvo = base + (size_t)(kb + 2) * 64 * HH;
                #pragma unroll
                for (int i = 0; i < 8; ++i) {
                    int id = gtid + 128 * i;
                    int arr = id >> 9, rem = id & 511, row = rem >> 3, ch = rem & 7;
                    const __half* src = arr ? g_V16 : g_K16;
                    CP_ASYNC16(ob + arr * 9216 + row * 144 + ch * 16,
                               src + kvo + (size_t)row * HH + ch * 8);
                }
                CP_COMMIT();
            }

            // ---- S = q16 K^T, 1-term fp16 (log2-domain) ----
            float S[8][4];
            #pragma unroll
            for (int j = 0; j < 8; ++j)
                #pragma unroll
                for (int q = 0; q < 4; ++q) S[j][q] = 0.0f;

            #pragma unroll
            for (int kk = 0; kk < 4; ++kk) {
                uint32_t Kf[8][2];
                #pragma unroll
                for (int n2 = 0; n2 < 4; ++n2) {
                    uint32_t a = sb + A_K + (n2 * 16 + li + nh8) * 144 + kk * 32 + kh16;
                    ldsm_x4(&Kf[2 * n2][0], a);
                }
                #pragma unroll
                for (int j = 0; j < 8; ++j)
                    mma_f16(S[j], q16[kk], Kf[j]);
            }

            if (kb == qb) {       // diagonal tile: causal mask (local coords)
                const int rA = wg * 16 + g, rB = rA + 8;
                #pragma unroll
                for (int j = 0; j < 8; ++j) {
                    const int c0 = j * 8 + t2;
                    if (c0 > rA)     S[j][0] = -1e30f;
                    if (c0 + 1 > rA) S[j][1] = -1e30f;
                    if (c0 > rB)     S[j][2] = -1e30f;
                    if (c0 + 1 > rB) S[j][3] = -1e30f;
                }
            }

            // ---- online softmax, exp2 domain; P emitted as fp16x2 frags ----
            float mx0 = fmaxf(S[0][0], S[0][1]);
            float mx1 = fmaxf(S[0][2], S[0][3]);
            #pragma unroll
            for (int j = 1; j < 8; ++j) {
                mx0 = fmaxf(mx0, fmaxf(S[j][0], S[j][1]));
                mx1 = fmaxf(mx1, fmaxf(S[j][2], S[j][3]));
            }
            mx0 = fmaxf(mx0, __shfl_xor_sync(0xffffffffu, mx0, 1));
            mx0 = fmaxf(mx0, __shfl_xor_sync(0xffffffffu, mx0, 2));
            mx1 = fmaxf(mx1, __shfl_xor_sync(0xffffffffu, mx1, 1));
            mx1 = fmaxf(mx1, __shfl_xor_sync(0xffffffffu, mx1, 2));
            const float mn0 = fmaxf(m_[0], mx0);
            const float mn1 = fmaxf(m_[1], mx1);
            const float corr0 = ex2f(m_[0] - mn0);
            const float corr1 = ex2f(m_[1] - mn1);
            m_[0] = mn0; m_[1] = mn1;

            uint32_t EA[8], EB[8];
            #pragma unroll
            for (int j = 0; j < 8; ++j) {
                EA[j] = ex2_h2(pack_h2(S[j][0] - mn0, S[j][1] - mn0));
                EB[j] = ex2_h2(pack_h2(S[j][2] - mn1, S[j][3] - mn1));
            }
            #pragma unroll
            for (int j = 0; j < 8; ++j) {
                O[j][0] *= corr0; O[j][1] *= corr0;
                O[j][2] *= corr1; O[j][3] *= corr1;
            }

            // ---- O += P V (1-term fp16); l row-sums via ones-fragment mma ----
            float L[4] = {0.0f, 0.0f, 0.0f, 0.0f};
            #pragma unroll
            for (int kk = 0; kk < 4; ++kk) {
                uint32_t p[4] = {EA[2 * kk], EB[2 * kk], EA[2 * kk + 1], EB[2 * kk + 1]};
                mma_f16(L, p, ones2);       // row-sums of this k16 slice of P
                uint32_t Vf[8][2];
                #pragma unroll
                for (int h2 = 0; h2 < 4; ++h2) {
                    uint32_t a = sb + A_V + (kk * 16 + li + sh8) * 144 + h2 * 32 + hh16;
                    ldsm_x4_t(&Vf[2 * h2][0], a);
                }
                #pragma unroll
                for (int j = 0; j < 8; ++j)
                    mma_f16(O[j], p, Vf[j]);
            }
            l_[0] = l_[0] * corr0 + L[0];
            l_[1] = l_[1] * corr1 + L[2];

            CP_WAIT0();
            GBAR(1 + grp);       // group-local barrier (stages are per-group)
        }

        // ---- merge partials: group1 -> smem, group0 combines + writes ----
        __syncthreads();         // all tiles done; stage smem reusable
        float* mb = (float*)(smem + A_ST0);
        if (grp == 1) {
            float* slot = mb + gtid * 36;
            #pragma unroll
            for (int j = 0; j < 8; ++j)
                #pragma unroll
                for (int q = 0; q < 4; ++q) slot[j * 4 + q] = O[j][q];
            slot[32] = m_[0]; slot[33] = m_[1];
            slot[34] = l_[0]; slot[35] = l_[1];
        }
        __syncthreads();
        if (grp == 0) {
            const float* slot = mb + gtid * 36;
            const float m1a = slot[32], m1b = slot[33];
            const float l1a = slot[34], l1b = slot[35];
            const float mnA = fmaxf(m_[0], m1a), mnB = fmaxf(m_[1], m1b);
            const float c00 = ex2f(m_[0] - mnA), c01 = ex2f(m1a - mnA);
            const float c10 = ex2f(m_[1] - mnB), c11 = ex2f(m1b - mnB);
            const float iA = 1.0f / (l_[0] * c00 + l1a * c01);
            const float iB = 1.0f / (l_[1] * c10 + l1b * c11);
            const int rowA = qb * 64 + wg * 16 + g;
            float* ob = out + (size_t)b * SS * HH;
            #pragma unroll
            for (int j = 0; j < 8; ++j) {
                const int col = j * 8 + t2;
                float2 v0, v1;
                v0.x = (O[j][0] * c00 + slot[j * 4 + 0] * c01) * iA;
                v0.y = (O[j][1] * c00 + slot[j * 4 + 1] * c01) * iA;
                v1.x = (O[j][2] * c10 + slot[j * 4 + 2] * c11) * iB;
                v1.y = (O[j][3] * c10 + slot[j * 4 + 3] * c11) * iB;
                *(float2*)&ob[(size_t)rowA * HH + col] = v0;
                *(float2*)&ob[(size_t)(rowA + 8) * HH + col] = v1;
            }
        }
        __syncthreads();         // before next pass overwrites Q smem / stages
    }
}

// ---------------------------------------------------------------------------
extern "C" void kernel_launch(void* const* d_in, const int* in_sizes, int n_in,
                              void* d_out, int out_size)
{
    (void)in_sizes; (void)n_in; (void)out_size;
    const float* x  = (const float*)d_in[0];
    const float* Wq = (const float*)d_in[1];
    const float* Wk = (const float*)d_in[2];
    const float* Wv = (const float*)d_in[3];
    float* out = (float*)d_out;

    static int attr_set = 0;
    const int gemm_smem = 3 * G_STG;                // 76800 -> 2 CTAs/SM
    const int attn_smem = A_SMEM;                   // 82944 -> 2 CTAs/SM
    if (!attr_set) {
        cudaFuncSetAttribute(qkv_mma_kernel,
                             cudaFuncAttributeMaxDynamicSharedMemorySize, gemm_smem);
        cudaFuncSetAttribute(attn_mma_kernel,
                             cudaFuncAttributeMaxDynamicSharedMemorySize, attn_smem);
        attr_set = 1;
    }

    wconv_kernel<<<(NTOT * DD + 255) / 256, 256>>>(Wq, Wk, Wv);
    qkv_mma_kernel<<<SS * BB / 64, 256, gemm_smem>>>(x);
    attn_mma_kernel<<<dim3(32, 4), 256, attn_smem>>>(out);
}